// round 9
// baseline (speedup 1.0000x reference)
#include <cuda_runtime.h>
#include <cuda_fp16.h>
#include <math.h>
#include <stdint.h>

#define NN 50000
#define NE 800000
#define C 96
#define KW 384            // total K = 4*C  (T0|T1|T2|T3)
#define FW 288            // fused GEMM output width = 3*C
#define BN_EPS 1e-5f
#define TILES 391         // ceil(NN/128)
#define EB 24             // SpMM edges per cp.async batch

// ---------------- scratch (device globals; no allocation allowed) ----------------
__device__ __half g_Th[(size_t)NN * KW];   // fp16 mirror of T0..T3, row-major [N][384]
__device__ float g_T1[NN * C];             // fp32 T1 (subtraction term for T3)
__device__ float g_h[NN * C];              // pre-BN output
__device__ float g_deg[NN];
__device__ float g_dis[NN];
__device__ int   g_cnt[NN];
__device__ int   g_ptr[NN + 1];
__device__ int   g_cur[NN];
__device__ int   g_bsum[64];
__device__ int2  g_epair[NE];              // raw (row, col)
__device__ int2  g_epack[NE];              // CSR-ordered (row, bitcast weight)
__device__ int   g_is64;
__device__ float g_A3[KW * 3];
__device__ float g_cs[3 * C];              // reordered: block b = scale 2-b
__device__ float g_lconst[3];
__device__ float g_sum[C];
__device__ float g_sumsq[C];
__device__ __half g_Uf16[FW * KW];         // n-major [288 n][384 k]; N order (s2|s1|s0); zero blocks never written

// ---------------- small helpers ----------------
__device__ __forceinline__ uint32_t smem_u32(const void* p) {
    uint32_t a;
    asm("{ .reg .u64 t; cvta.to.shared.u64 t, %1; cvt.u32.u64 %0, t; }" : "=r"(a) : "l"(p));
    return a;
}
#define CP16(dst, src) asm volatile("cp.async.cg.shared.global [%0], [%1], 16;" :: "r"(dst), "l"(src) : "memory")
#define CPCOMMIT()     asm volatile("cp.async.commit_group;" ::: "memory")
#define CPWAIT(n)      asm volatile("cp.async.wait_group %0;" :: "n"(n) : "memory")

__device__ __forceinline__ void mma16816(float* d, const uint32_t* a, const uint32_t* b) {
    asm volatile(
        "mma.sync.aligned.m16n8k16.row.col.f32.f16.f16.f32 "
        "{%0,%1,%2,%3}, {%4,%5,%6,%7}, {%8,%9}, {%0,%1,%2,%3};"
        : "+f"(d[0]), "+f"(d[1]), "+f"(d[2]), "+f"(d[3])
        : "r"(a[0]), "r"(a[1]), "r"(a[2]), "r"(a[3]), "r"(b[0]), "r"(b[1]));
}

// ---------------- zero + dtype detect + x -> fp16 T0 slice ----------------
__global__ void k_zero(const float* __restrict__ x, const int* __restrict__ ei32) {
    int i = blockIdx.x * blockDim.x + threadIdx.x;
    if (i < NN) { g_deg[i] = 0.f; g_cnt[i] = 0; }
    if (i < KW * 3) g_A3[i] = 0.f;
    if (i < C) { g_sum[i] = 0.f; g_sumsq[i] = 0.f; }
    if (i < NN * 48) {
        int n = i / 48, cp = i - (i / 48) * 48;
        float2 v = *(const float2*)(x + (size_t)n * 96 + cp * 2);
        *(__half2*)(g_Th + (size_t)n * KW + cp * 2) = __floats2half2_rn(v.x, v.y);
    }
    if (blockIdx.x == 0) {
        __shared__ int nz;
        if (threadIdx.x == 0) nz = 0;
        __syncthreads();
        int v = ei32[threadIdx.x * 2 + 1];
        if (v != 0) atomicAdd(&nz, 1);
        __syncthreads();
        if (threadIdx.x == 0) g_is64 = (nz == 0) ? 1 : 0;
    }
}

// ---------------- unpack edges + degree histogram (fused) ----------------
__global__ void k_edges(const void* __restrict__ ei) {
    int e = blockIdx.x * blockDim.x + threadIdx.x;
    if (e >= NE) return;
    int r, c;
    if (g_is64) {
        const long long* p = (const long long*)ei;
        r = (int)p[e];
        c = (int)p[NE + e];
    } else {
        const int* p = (const int*)ei;
        r = p[e];
        c = p[NE + e];
    }
    if ((unsigned)r >= NN) r = 0;
    if ((unsigned)c >= NN) c = 0;
    g_epair[e] = make_int2(r, c);
    atomicAdd(&g_deg[r], 1.0f);
    atomicAdd(&g_cnt[c], 1);
}

// ---------------- exclusive scan of g_cnt -> g_ptr  (+ dis computation) ----------------
__global__ void k_scan_local() {
    __shared__ int wsum[8];
    int t = threadIdx.x;
    int base = blockIdx.x * 1024 + t * 4;
    int v[4];
#pragma unroll
    for (int j = 0; j < 4; j++) {
        int idx = base + j;
        v[j] = (idx < NN) ? g_cnt[idx] : 0;
        if (idx < NN) {
            float d = g_deg[idx];
            g_dis[idx] = (d > 0.f) ? rsqrtf(d) : 0.f;
        }
    }
    int tsum = v[0] + v[1] + v[2] + v[3];
    int lane = t & 31, wid = t >> 5;
    int x = tsum;
#pragma unroll
    for (int o = 1; o < 32; o <<= 1) {
        int y = __shfl_up_sync(0xffffffffu, x, o);
        if (lane >= o) x += y;
    }
    if (lane == 31) wsum[wid] = x;
    __syncthreads();
    if (wid == 0) {
        int wv = (lane < 8) ? wsum[lane] : 0;
#pragma unroll
        for (int o = 1; o < 8; o <<= 1) {
            int y = __shfl_up_sync(0xffffffffu, wv, o);
            if (lane >= o) wv += y;
        }
        if (lane < 8) wsum[lane] = wv;
    }
    __syncthreads();
    int exc = x - tsum + ((wid > 0) ? wsum[wid - 1] : 0);
    int run = exc;
#pragma unroll
    for (int j = 0; j < 4; j++) {
        int idx = base + j;
        if (idx < NN) g_ptr[idx] = run;
        run += v[j];
    }
    if (t == 255) g_bsum[blockIdx.x] = run;
}

__global__ void k_scan_add() {
    __shared__ int accs;
    int i = blockIdx.x * blockDim.x + threadIdx.x;
    if (threadIdx.x == 0) {
        int b = (blockIdx.x * blockDim.x) >> 10;
        int a = 0;
        for (int t = 0; t < b; t++) a += g_bsum[t];
        accs = a;
    }
    __syncthreads();
    if (i < NN) {
        int p = g_ptr[i] + accs;
        g_ptr[i] = p;
        g_cur[i] = p;
    }
    if (i == 0) g_ptr[NN] = NE;
}

__global__ void k_scatter() {
    int e = blockIdx.x * blockDim.x + threadIdx.x;
    if (e >= NE) return;
    int2 p = g_epair[e];
    int pos = atomicAdd(&g_cur[p.y], 1);
    g_epack[pos] = make_int2(p.x, __float_as_int(-(g_dis[p.x] * g_dis[p.y])));
}

// ---------------- precompute combined weights (parallelized: 36 + 1 blocks) ----------------
// N-order reversed: scale s lives in block (2-s).
__global__ void k_precompU(const float* __restrict__ w2, const float* __restrict__ w3,
                           const float* __restrict__ w4, const float* __restrict__ fus_w,
                           const float* __restrict__ attn_w,
                           const float* __restrict__ b2, const float* __restrict__ b3,
                           const float* __restrict__ b4, const float* __restrict__ attn_b) {
    int b = blockIdx.x;
    if (b == 36) {
        for (int t = threadIdx.x; t < 3 * C; t += blockDim.x) {
            int s = t / C, j = t - s * C;
            const float* bs = (s == 0) ? b2 : (s == 1) ? b3 : b4;
            float acc = 0.f;
            for (int m = 0; m < C; m++) acc += bs[m] * fus_w[(s * C + m) * C + j];
            g_cs[(2 - s) * C + j] = acc;
        }
        if (threadIdx.x < 3) {
            int t = threadIdx.x;
            float acc = attn_b[t];
            for (int s = 0; s < 3; s++) {
                const float* bs = (s == 0) ? b2 : (s == 1) ? b3 : b4;
                for (int m = 0; m < C; m++) acc += bs[m] * attn_w[(s * C + m) * 3 + t];
            }
            g_lconst[t] = acc;
        }
        return;
    }
    const int Ss[9] = {0, 0, 1, 1, 1, 2, 2, 2, 2};
    const int Kk[9] = {0, 1, 0, 1, 2, 0, 1, 2, 3};
    int wb = b >> 2, qr = b & 3;          // weight-block, row-quarter
    int s = Ss[wb], k = Kk[wb];
    const float* w = ((s == 0) ? w2 : (s == 1) ? w3 : w4) + k * C * C;
    __shared__ float fusS[C * C];
    for (int i = threadIdx.x; i < C * C; i += blockDim.x)
        fusS[i] = fus_w[s * C * C + i];
    __syncthreads();
    // rows i in [qr*24, qr*24+24)
    for (int id = threadIdx.x; id < 24 * C; id += blockDim.x) {
        int i = qr * 24 + id / C, j = id % C;
        float acc = 0.f;
#pragma unroll 8
        for (int m = 0; m < C; m++) acc += w[i * C + m] * fusS[m * C + j];
        g_Uf16[(size_t)((2 - s) * C + j) * KW + (k * C + i)] = __float2half(acc);
    }
    for (int id = threadIdx.x; id < 24 * 3; id += blockDim.x) {
        int i = qr * 24 + id / 3, j = id % 3;
        float acc = 0.f;
#pragma unroll 8
        for (int m = 0; m < C; m++) acc += w[i * C + m] * attn_w[(s * C + m) * 3 + j];
        atomicAdd(&g_A3[(k * C + i) * 3 + j], acc);
    }
}

// ---------------- SpMM: warp per node, cp.async-staged batches of EB edges ----------------
#define SPMM_ACC(vv, ww)                                                                    \
    {                                                                                       \
        const __half2* hp = (const __half2*)&(vv);                                          \
        _Pragma("unroll") for (int q = 0; q < 4; q++) {                                     \
            float2 f = __half22float2(hp[q]);                                               \
            acc[2 * q]     += (ww) * f.x;                                                   \
            acc[2 * q + 1] += (ww) * f.y;                                                   \
        }                                                                                   \
    }

// per-warp smem: EB*192 data + EB*8 idx = 4800 bytes; 8 warps -> 38400 bytes static
__global__ void __launch_bounds__(256) k_spmm(int in_byte_off, const float* __restrict__ sub,
                                              float* __restrict__ outf, int out_half_off, int first) {
    __shared__ __align__(16) unsigned char sbuf[8][EB * 192 + EB * 8];
    int warp = (blockIdx.x * blockDim.x + threadIdx.x) >> 5;
    int lane = threadIdx.x & 31;
    int wloc = (threadIdx.x >> 5);
    if (warp >= NN) return;
    unsigned char* dbuf = sbuf[wloc];
    int2* ibuf = (int2*)(sbuf[wloc] + EB * 192);
    int s = g_ptr[warp], e = g_ptr[warp + 1];
    float acc[8];
#pragma unroll
    for (int q = 0; q < 8; q++) acc[q] = 0.f;
    const char* basep = (const char*)g_Th + in_byte_off;
    bool act = lane < 24;
    int gl = lane % 12, gsel = lane / 12;

    for (int base = s; base < e; base += EB) {
        // 1) idx load: lanes 0..EB-1 fetch (row, weight); pad with weight 0
        int2 pk = make_int2(0, 0);
        if (lane < EB) {
            int idx = base + lane;
            if (idx < e) pk = g_epack[idx];
            ibuf[lane] = pk;
        }
        __syncwarp();
        // 2) stage EB rows (192B each) via cp.async: 288 chunks = 9 warp-wide issues
#pragma unroll
        for (int i = 0; i < 9; i++) {
            int id = i * 32 + lane;            // 0..287
            int ed = id / 12, part = id - ed * 12;
            int row = __shfl_sync(0xffffffffu, pk.x, ed);
            const char* src = basep + (size_t)row * 768 + part * 16;
            uint32_t dst = smem_u32(dbuf + ed * 192 + part * 16);
            CP16(dst, src);
        }
        CPCOMMIT();
        CPWAIT(0);
        __syncwarp();
        // 3) accumulate from smem, 2 edges per step
#pragma unroll
        for (int j = 0; j < EB; j += 2) {
            if (act) {
                int eidx = j + gsel;
                int2 p = ibuf[eidx];
                float w = __int_as_float(p.y);
                uint4 v = *(const uint4*)(dbuf + eidx * 192 + gl * 16);
                SPMM_ACC(v, w);
            }
        }
        __syncwarp();
    }
    // fold group 1 (lanes 12-23) into group 0 (lanes 0-11)
#pragma unroll
    for (int q = 0; q < 8; q++) {
        float o = __shfl_down_sync(0xffffffffu, acc[q], 12);
        acc[q] += o;
    }
    if (lane < 12) {
        if (!first) {
            const float* sb = sub + (size_t)warp * 96 + gl * 8;
#pragma unroll
            for (int q = 0; q < 8; q++) acc[q] = 2.f * acc[q] - sb[q];
        }
        __half2 h[4];
#pragma unroll
        for (int q = 0; q < 4; q++) h[q] = __floats2half2_rn(acc[2 * q], acc[2 * q + 1]);
        *(uint4*)((char*)g_Th + (size_t)warp * 768 + out_half_off * 2 + gl * 16) = *(const uint4*)h;
        if (outf) {
            float4* of = (float4*)(outf + (size_t)warp * 96 + gl * 8);
            of[0] = make_float4(acc[0], acc[1], acc[2], acc[3]);
            of[1] = make_float4(acc[4], acc[5], acc[6], acc[7]);
        }
    }
}

// ---------------- fused GEMM + logits + softmax combine + BN partials ----------------
// CTA tile 128(M) x 288(N), 512 threads = 16 warps (4m x 4n), warp tile 32x72.
// K = 6 chunks of 64; per-chunk active N-width W = {288,288,288,192,192,96}.
#define SM_A_BYTES (2 * 128 * 72 * 2)                       // 36864
#define SM_B_OFF SM_A_BYTES
#define SM_B_BYTES (2 * 288 * 72 * 2)                       // 82944
#define STG_PITCH 292
#define SM_A3_OFF (128 * STG_PITCH * 4)                     // 149504 (above stage)
#define SM_LS_OFF (SM_A3_OFF + KW * 3 * 4)                  // 154112
#define SM_WS_OFF (SM_LS_OFF + 128 * 3 * 4)                 // 155648
#define FUSED_SMEM (SM_WS_OFF + 128 * 3 * 4)                // 157184

template <int WC>
__device__ __forceinline__ void do_chunk(const __half* __restrict__ Ab,
                                         const __half* __restrict__ Bb,
                                         float (&acc)[2][9][4],
                                         int wm, int wn, int gid, int tq) {
    if (WC < 288 && wn * 72 >= WC) return;
#pragma unroll
    for (int k16 = 0; k16 < 4; k16++) {
        int kk = k16 * 16 + tq * 2;
        uint32_t afr[2][4];
#pragma unroll
        for (int mt = 0; mt < 2; mt++) {
            int r = wm * 32 + mt * 16 + gid;
            afr[mt][0] = *(const uint32_t*)(Ab + r * 72 + kk);
            afr[mt][1] = *(const uint32_t*)(Ab + (r + 8) * 72 + kk);
            afr[mt][2] = *(const uint32_t*)(Ab + r * 72 + kk + 8);
            afr[mt][3] = *(const uint32_t*)(Ab + (r + 8) * 72 + kk + 8);
        }
#pragma unroll
        for (int nt = 0; nt < 9; nt++) {
            if (WC < 288 && wn * 72 + nt * 8 >= WC) break;
            int n = wn * 72 + nt * 8 + gid;
            uint32_t bfr[2];
            bfr[0] = *(const uint32_t*)(Bb + n * 72 + kk);
            bfr[1] = *(const uint32_t*)(Bb + n * 72 + kk + 8);
            mma16816(acc[0][nt], afr[0], bfr);
            mma16816(acc[1][nt], afr[1], bfr);
        }
    }
}

__global__ void __launch_bounds__(512, 1) k_fused(const float* __restrict__ fus_b) {
    extern __shared__ unsigned char dyn[];
    __half* As = (__half*)dyn;                    // [2][128][72]
    __half* Bs = (__half*)(dyn + SM_B_OFF);       // [2][288][72]
    float* A3s = (float*)(dyn + SM_A3_OFF);       // [384][3]
    float* Ls = (float*)(dyn + SM_LS_OFF);        // [128][3]
    float* Ws = (float*)(dyn + SM_WS_OFF);        // [128][3]
    float* stage = (float*)dyn;                   // [128][292] (epilogue, overlaps A/B)
    float* bnS = A3s;                             // [192] (epilogue, overlaps A3s)
    uint32_t smA = smem_u32(As);
    uint32_t smB = smem_u32(Bs);

    int tid = threadIdx.x;
    int lane = tid & 31, wid = tid >> 5;
    int wm = wid & 3, wn = wid >> 2;
    int gid = lane >> 2, tq = lane & 3;
    int m0 = blockIdx.x * 128;

    for (int i = tid; i < KW * 3; i += 512) A3s[i] = g_A3[i];

    const int Warr[6] = {288, 288, 288, 192, 192, 96};

#define LOAD_A(chunk, buf)                                                                  \
    {                                                                                       \
        _Pragma("unroll") for (int i = 0; i < 2; i++) {                                     \
            int idx = tid + i * 512;                                                        \
            int row = idx >> 3, seg = idx & 7;                                              \
            int srow = m0 + row; if (srow >= NN) srow = NN - 1;                             \
            const __half* src = g_Th + (size_t)srow * KW + (chunk) * 64 + seg * 8;          \
            uint32_t dst = smA + (((buf) * 128 + row) * 72 + seg * 8) * 2;                  \
            CP16(dst, src);                                                                 \
        }                                                                                   \
    }
#define LOAD_B(chunk, buf, wb)                                                              \
    {                                                                                       \
        _Pragma("unroll") for (int i = 0; i < 5; i++) {                                     \
            int idx = tid + i * 512;                                                        \
            int row = idx >> 3, seg = idx & 7;                                              \
            if (row < (wb)) {                                                               \
                const __half* src = g_Uf16 + (size_t)row * KW + (chunk) * 64 + seg * 8;     \
                uint32_t dst = smB + (((buf) * 288 + row) * 72 + seg * 8) * 2;              \
                CP16(dst, src);                                                             \
            }                                                                               \
        }                                                                                   \
    }

    float acc[2][9][4];
#pragma unroll
    for (int mt = 0; mt < 2; mt++)
#pragma unroll
        for (int nt = 0; nt < 9; nt++)
#pragma unroll
            for (int q = 0; q < 4; q++) acc[mt][nt][q] = 0.f;
    float Lacc = 0.f;
    int lr = tid / 3, lj = tid - (tid / 3) * 3;   // logits assignment (tid<384)

    LOAD_A(0, 0);
    LOAD_B(0, 0, 288);
    CPCOMMIT();

    for (int c = 0; c < 6; c++) {
        int buf = c & 1;
        if (c + 1 < 6) {
            LOAD_A(c + 1, buf ^ 1);
            LOAD_B(c + 1, buf ^ 1, Warr[c + 1]);
            CPCOMMIT();
            CPWAIT(1);
        } else {
            CPWAIT(0);
        }
        __syncthreads();

        const __half* Ab = As + (size_t)buf * 128 * 72;
        const __half* Bb = Bs + (size_t)buf * 288 * 72;
        if (c < 3)      do_chunk<288>(Ab, Bb, acc, wm, wn, gid, tq);
        else if (c < 5) do_chunk<192>(Ab, Bb, acc, wm, wn, gid, tq);
        else            do_chunk<96>(Ab, Bb, acc, wm, wn, gid, tq);

        // logits on the same A chunk (half2 loads, fp32 accumulate)
        if (tid < 384) {
            const __half2* Ar2 = (const __half2*)(Ab + lr * 72);
            const float* A3c = A3s + c * 192 + lj;
#pragma unroll 8
            for (int kk2 = 0; kk2 < 32; kk2++) {
                float2 f = __half22float2(Ar2[kk2]);
                Lacc += f.x * A3c[kk2 * 6] + f.y * A3c[kk2 * 6 + 3];
            }
        }
        __syncthreads();
    }

    // ---- epilogue ----
    if (tid < 384) Ls[tid] = Lacc;
    if (tid < 192) bnS[tid] = 0.f;
#pragma unroll
    for (int mt = 0; mt < 2; mt++) {
        int row = wm * 32 + mt * 16 + gid;
#pragma unroll
        for (int nt = 0; nt < 9; nt++) {
            int cc = wn * 72 + nt * 8 + tq * 2;
            *(float2*)(stage + row * STG_PITCH + cc) = make_float2(acc[mt][nt][0], acc[mt][nt][1]);
            *(float2*)(stage + (row + 8) * STG_PITCH + cc) = make_float2(acc[mt][nt][2], acc[mt][nt][3]);
        }
    }
    __syncthreads();

    if (tid < 128) {
        float l0 = Ls[tid * 3 + 0] + g_lconst[0];
        float l1 = Ls[tid * 3 + 1] + g_lconst[1];
        float l2 = Ls[tid * 3 + 2] + g_lconst[2];
        float m = fmaxf(l0, fmaxf(l1, l2));
        float e0 = __expf(l0 - m), e1 = __expf(l1 - m), e2 = __expf(l2 - m);
        float inv = 1.f / (e0 + e1 + e2);
        Ws[tid * 3 + 0] = e0 * inv;
        Ws[tid * 3 + 1] = e1 * inv;
        Ws[tid * 3 + 2] = e2 * inv;
    }
    __syncthreads();

    if (tid < 384) {
        int c = tid % 96, q = tid / 96;
        // N-block b holds scale 2-b
        float cs0 = g_cs[c], cs1 = g_cs[96 + c], cs2 = g_cs[192 + c];
        float fb = fus_b[c];
        float lsum = 0.f, lsq = 0.f;
        for (int r = q * 32; r < q * 32 + 32; r++) {
            int m = m0 + r;
            if (m >= NN) break;
            float w2s = Ws[r * 3 + 2];   // scale2 -> block 0
            float w1s = Ws[r * 3 + 1];   // scale1 -> block 1
            float w0s = Ws[r * 3 + 0];   // scale0 -> block 2
            const float* f = stage + r * STG_PITCH;
            float h = w2s * (f[c] + cs0) + w1s * (f[96 + c] + cs1) + w0s * (f[192 + c] + cs2) + fb;
            g_h[(size_t)m * C + c] = h;
            lsum += h;
            lsq += h * h;
        }
        atomicAdd(&bnS[c], lsum);
        atomicAdd(&bnS[96 + c], lsq);
    }
    __syncthreads();
    if (tid < 96) {
        atomicAdd(&g_sum[tid], bnS[tid]);
        atomicAdd(&g_sumsq[tid], bnS[96 + tid]);
    }
#undef LOAD_A
#undef LOAD_B
}

// ---------------- BN finalize + normalize (fused) ----------------
__global__ void k_norm(const float* __restrict__ gamma, const float* __restrict__ beta,
                       float* __restrict__ out) {
    __shared__ float sc[C], sh[C];
    int tid = threadIdx.x;
    if (tid < C) {
        float mean = g_sum[tid] / (float)NN;
        float var = g_sumsq[tid] / (float)NN - mean * mean;
        var = fmaxf(var, 0.f);
        float s = gamma[tid] * rsqrtf(var + BN_EPS);
        sc[tid] = s;
        sh[tid] = beta[tid] - mean * s;
    }
    __syncthreads();
    int i = blockIdx.x * blockDim.x + tid;
    if (i >= NN * C) return;
    int c = i % C;
    out[i] = fmaxf(fmaf(g_h[i], sc[c], sh[c]), 0.f);
}

// ---------------- launch ----------------
extern "C" void kernel_launch(void* const* d_in, const int* in_sizes, int n_in,
                              void* d_out, int out_size) {
    const float* x        = (const float*)d_in[0];
    const void* ei        = d_in[1];
    const float* w2       = (const float*)d_in[2];
    const float* b2       = (const float*)d_in[3];
    const float* w3       = (const float*)d_in[4];
    const float* b3       = (const float*)d_in[5];
    const float* w4       = (const float*)d_in[6];
    const float* b4       = (const float*)d_in[7];
    const float* attn_w   = (const float*)d_in[8];
    const float* attn_b   = (const float*)d_in[9];
    const float* fus_w    = (const float*)d_in[10];
    const float* fus_b    = (const float*)d_in[11];
    const float* bn_gamma = (const float*)d_in[12];
    const float* bn_beta  = (const float*)d_in[13];
    float* out = (float*)d_out;

    static int smem_set = 0;
    if (!smem_set) {
        cudaFuncSetAttribute(k_fused, cudaFuncAttributeMaxDynamicSharedMemorySize, FUSED_SMEM);
        smem_set = 1;
    }

    float* T1 = nullptr;
    cudaGetSymbolAddress((void**)&T1, g_T1);

    k_zero<<<(NN * 48 + 255) / 256, 256>>>(x, (const int*)ei);
    k_edges<<<(NE + 255) / 256, 256>>>(ei);
    k_scan_local<<<49, 256>>>();
    k_scan_add<<<(NN + 255) / 256, 256>>>();
    k_scatter<<<(NE + 255) / 256, 256>>>();
    k_precompU<<<37, 256>>>(w2, w3, w4, fus_w, attn_w, b2, b3, b4, attn_b);

    // T1 = P(T0); T2 = 2*P(T1) - T0; T3 = 2*P(T2) - T1
    k_spmm<<<6250, 256>>>(0, nullptr, T1, 96, 1);
    k_spmm<<<6250, 256>>>(192, x, nullptr, 192, 0);
    k_spmm<<<6250, 256>>>(384, T1, nullptr, 288, 0);

    k_fused<<<TILES, 512, FUSED_SMEM>>>(fus_b);

    k_norm<<<(NN * C + 255) / 256, 256>>>(bn_gamma, bn_beta, out);
}

// round 11
// speedup vs baseline: 3.4550x; 3.4550x over previous
#include <cuda_runtime.h>
#include <cuda_fp16.h>
#include <math.h>
#include <stdint.h>

#define NN 50000
#define NE 800000
#define C 96
#define KW 384            // total K = 4*C  (T0|T1|T2|T3)
#define FW 288            // fused GEMM output width = 3*C
#define BN_EPS 1e-5f
#define TILES 391         // ceil(NN/128)

// ---------------- scratch (device globals; no allocation allowed) ----------------
__device__ __half g_Th[(size_t)NN * KW];   // fp16 mirror of T0..T3, row-major [N][384]
__device__ float g_T1[NN * C];             // fp32 T1 (subtraction term for T3)
__device__ float g_h[NN * C];              // pre-BN output
__device__ float g_deg[NN];
__device__ float g_dis[NN];
__device__ int   g_cnt[NN];
__device__ int   g_ptr[NN + 1];
__device__ int   g_cur[NN];
__device__ int   g_bsum[64];
__device__ int2  g_epair[NE];              // raw (row, col)
__device__ int2  g_epack[NE];              // CSR-ordered (row, bitcast weight)
__device__ int   g_is64;
__device__ float g_A3[KW * 3];
__device__ float g_cs[3 * C];              // reordered: block b = scale 2-b
__device__ float g_lconst[3];
__device__ float g_sum[C];
__device__ float g_sumsq[C];
__device__ __half g_Uf16[FW * KW];         // n-major [288 n][384 k]; N order (s2|s1|s0); zero blocks never written

// ---------------- small helpers ----------------
__device__ __forceinline__ uint32_t smem_u32(const void* p) {
    uint32_t a;
    asm("{ .reg .u64 t; cvta.to.shared.u64 t, %1; cvt.u32.u64 %0, t; }" : "=r"(a) : "l"(p));
    return a;
}
#define CP16(dst, src) asm volatile("cp.async.cg.shared.global [%0], [%1], 16;" :: "r"(dst), "l"(src) : "memory")
#define CPCOMMIT()     asm volatile("cp.async.commit_group;" ::: "memory")
#define CPWAIT(n)      asm volatile("cp.async.wait_group %0;" :: "n"(n) : "memory")

__device__ __forceinline__ void mma16816(float* d, const uint32_t* a, const uint32_t* b) {
    asm volatile(
        "mma.sync.aligned.m16n8k16.row.col.f32.f16.f16.f32 "
        "{%0,%1,%2,%3}, {%4,%5,%6,%7}, {%8,%9}, {%0,%1,%2,%3};"
        : "+f"(d[0]), "+f"(d[1]), "+f"(d[2]), "+f"(d[3])
        : "r"(a[0]), "r"(a[1]), "r"(a[2]), "r"(a[3]), "r"(b[0]), "r"(b[1]));
}

// ---------------- zero + dtype detect + x -> fp16 T0 slice ----------------
__global__ void k_zero(const float* __restrict__ x, const int* __restrict__ ei32) {
    int i = blockIdx.x * blockDim.x + threadIdx.x;
    if (i < NN) { g_deg[i] = 0.f; g_cnt[i] = 0; }
    if (i < KW * 3) g_A3[i] = 0.f;
    if (i < C) { g_sum[i] = 0.f; g_sumsq[i] = 0.f; }
    if (i < NN * 48) {
        int n = i / 48, cp = i - (i / 48) * 48;
        float2 v = *(const float2*)(x + (size_t)n * 96 + cp * 2);
        *(__half2*)(g_Th + (size_t)n * KW + cp * 2) = __floats2half2_rn(v.x, v.y);
    }
    if (blockIdx.x == 0) {
        __shared__ int nz;
        if (threadIdx.x == 0) nz = 0;
        __syncthreads();
        int v = ei32[threadIdx.x * 2 + 1];
        if (v != 0) atomicAdd(&nz, 1);
        __syncthreads();
        if (threadIdx.x == 0) g_is64 = (nz == 0) ? 1 : 0;
    }
}

// ---------------- unpack edges + degree histogram (fused) ----------------
__global__ void k_edges(const void* __restrict__ ei) {
    int e = blockIdx.x * blockDim.x + threadIdx.x;
    if (e >= NE) return;
    int r, c;
    if (g_is64) {
        const long long* p = (const long long*)ei;
        r = (int)p[e];
        c = (int)p[NE + e];
    } else {
        const int* p = (const int*)ei;
        r = p[e];
        c = p[NE + e];
    }
    if ((unsigned)r >= NN) r = 0;
    if ((unsigned)c >= NN) c = 0;
    g_epair[e] = make_int2(r, c);
    atomicAdd(&g_deg[r], 1.0f);
    atomicAdd(&g_cnt[c], 1);
}

// ---------------- exclusive scan of g_cnt -> g_ptr  (+ dis computation) ----------------
__global__ void k_scan_local() {
    __shared__ int wsum[8];
    int t = threadIdx.x;
    int base = blockIdx.x * 1024 + t * 4;
    int v[4];
#pragma unroll
    for (int j = 0; j < 4; j++) {
        int idx = base + j;
        v[j] = (idx < NN) ? g_cnt[idx] : 0;
        if (idx < NN) {
            float d = g_deg[idx];
            g_dis[idx] = (d > 0.f) ? rsqrtf(d) : 0.f;
        }
    }
    int tsum = v[0] + v[1] + v[2] + v[3];
    int lane = t & 31, wid = t >> 5;
    int x = tsum;
#pragma unroll
    for (int o = 1; o < 32; o <<= 1) {
        int y = __shfl_up_sync(0xffffffffu, x, o);
        if (lane >= o) x += y;
    }
    if (lane == 31) wsum[wid] = x;
    __syncthreads();
    if (wid == 0) {
        int wv = (lane < 8) ? wsum[lane] : 0;
#pragma unroll
        for (int o = 1; o < 8; o <<= 1) {
            int y = __shfl_up_sync(0xffffffffu, wv, o);
            if (lane >= o) wv += y;
        }
        if (lane < 8) wsum[lane] = wv;
    }
    __syncthreads();
    int exc = x - tsum + ((wid > 0) ? wsum[wid - 1] : 0);
    int run = exc;
#pragma unroll
    for (int j = 0; j < 4; j++) {
        int idx = base + j;
        if (idx < NN) g_ptr[idx] = run;
        run += v[j];
    }
    if (t == 255) g_bsum[blockIdx.x] = run;
}

__global__ void k_scan_add() {
    __shared__ int accs;
    int i = blockIdx.x * blockDim.x + threadIdx.x;
    if (threadIdx.x == 0) {
        int b = (blockIdx.x * blockDim.x) >> 10;
        int a = 0;
        for (int t = 0; t < b; t++) a += g_bsum[t];
        accs = a;
    }
    __syncthreads();
    if (i < NN) {
        int p = g_ptr[i] + accs;
        g_ptr[i] = p;
        g_cur[i] = p;
    }
    if (i == 0) g_ptr[NN] = NE;
}

__global__ void k_scatter() {
    int e = blockIdx.x * blockDim.x + threadIdx.x;
    if (e >= NE) return;
    int2 p = g_epair[e];
    int pos = atomicAdd(&g_cur[p.y], 1);
    g_epack[pos] = make_int2(p.x, __float_as_int(-(g_dis[p.x] * g_dis[p.y])));
}

// ---------------- precompute combined weights (parallelized: 36 + 1 blocks) ----------------
// N-order reversed: scale s lives in block (2-s).
__global__ void k_precompU(const float* __restrict__ w2, const float* __restrict__ w3,
                           const float* __restrict__ w4, const float* __restrict__ fus_w,
                           const float* __restrict__ attn_w,
                           const float* __restrict__ b2, const float* __restrict__ b3,
                           const float* __restrict__ b4, const float* __restrict__ attn_b) {
    int b = blockIdx.x;
    if (b == 36) {
        for (int t = threadIdx.x; t < 3 * C; t += blockDim.x) {
            int s = t / C, j = t - s * C;
            const float* bs = (s == 0) ? b2 : (s == 1) ? b3 : b4;
            float acc = 0.f;
            for (int m = 0; m < C; m++) acc += bs[m] * fus_w[(s * C + m) * C + j];
            g_cs[(2 - s) * C + j] = acc;
        }
        if (threadIdx.x < 3) {
            int t = threadIdx.x;
            float acc = attn_b[t];
            for (int s = 0; s < 3; s++) {
                const float* bs = (s == 0) ? b2 : (s == 1) ? b3 : b4;
                for (int m = 0; m < C; m++) acc += bs[m] * attn_w[(s * C + m) * 3 + t];
            }
            g_lconst[t] = acc;
        }
        return;
    }
    const int Ss[9] = {0, 0, 1, 1, 1, 2, 2, 2, 2};
    const int Kk[9] = {0, 1, 0, 1, 2, 0, 1, 2, 3};
    int wb = b >> 2, qr = b & 3;          // weight-block, row-quarter
    int s = Ss[wb], k = Kk[wb];
    const float* w = ((s == 0) ? w2 : (s == 1) ? w3 : w4) + k * C * C;
    __shared__ float fusS[C * C];
    for (int i = threadIdx.x; i < C * C; i += blockDim.x)
        fusS[i] = fus_w[s * C * C + i];
    __syncthreads();
    for (int id = threadIdx.x; id < 24 * C; id += blockDim.x) {
        int i = qr * 24 + id / C, j = id % C;
        float acc = 0.f;
#pragma unroll 8
        for (int m = 0; m < C; m++) acc += w[i * C + m] * fusS[m * C + j];
        g_Uf16[(size_t)((2 - s) * C + j) * KW + (k * C + i)] = __float2half(acc);
    }
    for (int id = threadIdx.x; id < 24 * 3; id += blockDim.x) {
        int i = qr * 24 + id / 3, j = id % 3;
        float acc = 0.f;
#pragma unroll 8
        for (int m = 0; m < C; m++) acc += w[i * C + m] * attn_w[(s * C + m) * 3 + j];
        atomicAdd(&g_A3[(k * C + i) * 3 + j], acc);
    }
}

// ---------------- SpMM: warp per node, 2 edges/LDG.128, pipelined index load ----------------
#define SPMM_ACC(vv, ww)                                                                    \
    {                                                                                       \
        const __half2* hp = (const __half2*)&(vv);                                          \
        _Pragma("unroll") for (int q = 0; q < 4; q++) {                                     \
            float2 f = __half22float2(hp[q]);                                               \
            acc[2 * q]     += (ww) * f.x;                                                   \
            acc[2 * q + 1] += (ww) * f.y;                                                   \
        }                                                                                   \
    }

__global__ void k_spmm(int in_byte_off, const float* __restrict__ sub,
                       float* __restrict__ outf, int out_half_off, int first) {
    int warp = (blockIdx.x * blockDim.x + threadIdx.x) >> 5;
    int lane = threadIdx.x & 31;
    if (warp >= NN) return;
    int s = g_ptr[warp], e = g_ptr[warp + 1];
    bool act = lane < 24;
    int gl = lane % 12;       // which uint4 of the 192B slice
    int gsel = lane / 12;     // which edge of the pair
    float acc[8];
#pragma unroll
    for (int q = 0; q < 8; q++) acc[q] = 0.f;
    const char* base = (const char*)g_Th + in_byte_off + gl * 16;

    int i = s;
    int2 pnext = make_int2(0, 0);
    if (act && i + 1 < e) pnext = g_epack[i + gsel];
    for (; i + 1 < e; i += 2) {
        int2 pcur = pnext;
        if (act && i + 3 < e) pnext = g_epack[i + 2 + gsel];   // prefetch next pair
        if (act) {
            uint4 v = *(const uint4*)(base + (size_t)pcur.x * 768);
            float w = __int_as_float(pcur.y);
            SPMM_ACC(v, w);
        }
    }
    if (i < e && lane < 12) {
        int2 p = g_epack[i];
        uint4 v = *(const uint4*)(base + (size_t)p.x * 768);
        float w = __int_as_float(p.y);
        SPMM_ACC(v, w);
    }
    // fold group 1 (lanes 12-23) into group 0 (lanes 0-11)
#pragma unroll
    for (int q = 0; q < 8; q++) {
        float o = __shfl_down_sync(0xffffffffu, acc[q], 12);
        acc[q] += o;
    }
    if (lane < 12) {
        if (!first) {
            const float* sb = sub + (size_t)warp * 96 + gl * 8;
#pragma unroll
            for (int q = 0; q < 8; q++) acc[q] = 2.f * acc[q] - sb[q];
        }
        __half2 h[4];
#pragma unroll
        for (int q = 0; q < 4; q++) h[q] = __floats2half2_rn(acc[2 * q], acc[2 * q + 1]);
        *(uint4*)((char*)g_Th + (size_t)warp * 768 + out_half_off * 2 + gl * 16) = *(const uint4*)h;
        if (outf) {
            float4* of = (float4*)(outf + (size_t)warp * 96 + gl * 8);
            of[0] = make_float4(acc[0], acc[1], acc[2], acc[3]);
            of[1] = make_float4(acc[4], acc[5], acc[6], acc[7]);
        }
    }
}

// ---------------- fused GEMM + logits + softmax combine + BN partials ----------------
// CTA tile 128(M) x 288(N), 512 threads = 16 warps (4m x 4n), warp tile 32x72.
// K = 6 chunks of 64; per-chunk active N-width W = {288,288,288,192,192,96}.
#define SM_A_BYTES (2 * 128 * 72 * 2)                       // 36864
#define SM_B_OFF SM_A_BYTES
#define SM_B_BYTES (2 * 288 * 72 * 2)                       // 82944
#define STG_PITCH 292
#define SM_A3_OFF (128 * STG_PITCH * 4)                     // 149504 (above stage)
#define SM_LS_OFF (SM_A3_OFF + KW * 3 * 4)                  // 154112
#define SM_WS_OFF (SM_LS_OFF + 128 * 3 * 4)                 // 155648
#define FUSED_SMEM (SM_WS_OFF + 128 * 3 * 4)                // 157184

template <int WC>
__device__ __forceinline__ void do_chunk(const __half* __restrict__ Ab,
                                         const __half* __restrict__ Bb,
                                         float (&acc)[2][9][4],
                                         int wm, int wn, int gid, int tq) {
    if (WC < 288 && wn * 72 >= WC) return;
#pragma unroll
    for (int k16 = 0; k16 < 4; k16++) {
        int kk = k16 * 16 + tq * 2;
        uint32_t afr[2][4];
#pragma unroll
        for (int mt = 0; mt < 2; mt++) {
            int r = wm * 32 + mt * 16 + gid;
            afr[mt][0] = *(const uint32_t*)(Ab + r * 72 + kk);
            afr[mt][1] = *(const uint32_t*)(Ab + (r + 8) * 72 + kk);
            afr[mt][2] = *(const uint32_t*)(Ab + r * 72 + kk + 8);
            afr[mt][3] = *(const uint32_t*)(Ab + (r + 8) * 72 + kk + 8);
        }
#pragma unroll
        for (int nt = 0; nt < 9; nt++) {
            if (WC < 288 && wn * 72 + nt * 8 >= WC) break;
            int n = wn * 72 + nt * 8 + gid;
            uint32_t bfr[2];
            bfr[0] = *(const uint32_t*)(Bb + n * 72 + kk);
            bfr[1] = *(const uint32_t*)(Bb + n * 72 + kk + 8);
            mma16816(acc[0][nt], afr[0], bfr);
            mma16816(acc[1][nt], afr[1], bfr);
        }
    }
}

__global__ void __launch_bounds__(512, 1) k_fused(const float* __restrict__ fus_b) {
    extern __shared__ unsigned char dyn[];
    __half* As = (__half*)dyn;                    // [2][128][72]
    __half* Bs = (__half*)(dyn + SM_B_OFF);       // [2][288][72]
    float* A3s = (float*)(dyn + SM_A3_OFF);       // [384][3]
    float* Ls = (float*)(dyn + SM_LS_OFF);        // [128][3]
    float* Ws = (float*)(dyn + SM_WS_OFF);        // [128][3]
    float* stage = (float*)dyn;                   // [128][292] (epilogue, overlaps A/B)
    float* bnS = A3s;                             // [192] (epilogue, overlaps A3s)
    uint32_t smA = smem_u32(As);
    uint32_t smB = smem_u32(Bs);

    int tid = threadIdx.x;
    int lane = tid & 31, wid = tid >> 5;
    int wm = wid & 3, wn = wid >> 2;
    int gid = lane >> 2, tq = lane & 3;
    int m0 = blockIdx.x * 128;

    for (int i = tid; i < KW * 3; i += 512) A3s[i] = g_A3[i];

    const int Warr[6] = {288, 288, 288, 192, 192, 96};

#define LOAD_A(chunk, buf)                                                                  \
    {                                                                                       \
        _Pragma("unroll") for (int i = 0; i < 2; i++) {                                     \
            int idx = tid + i * 512;                                                        \
            int row = idx >> 3, seg = idx & 7;                                              \
            int srow = m0 + row; if (srow >= NN) srow = NN - 1;                             \
            const __half* src = g_Th + (size_t)srow * KW + (chunk) * 64 + seg * 8;          \
            uint32_t dst = smA + (((buf) * 128 + row) * 72 + seg * 8) * 2;                  \
            CP16(dst, src);                                                                 \
        }                                                                                   \
    }
#define LOAD_B(chunk, buf, wb)                                                              \
    {                                                                                       \
        _Pragma("unroll") for (int i = 0; i < 5; i++) {                                     \
            int idx = tid + i * 512;                                                        \
            int row = idx >> 3, seg = idx & 7;                                              \
            if (row < (wb)) {                                                               \
                const __half* src = g_Uf16 + (size_t)row * KW + (chunk) * 64 + seg * 8;     \
                uint32_t dst = smB + (((buf) * 288 + row) * 72 + seg * 8) * 2;              \
                CP16(dst, src);                                                             \
            }                                                                               \
        }                                                                                   \
    }

    float acc[2][9][4];
#pragma unroll
    for (int mt = 0; mt < 2; mt++)
#pragma unroll
        for (int nt = 0; nt < 9; nt++)
#pragma unroll
            for (int q = 0; q < 4; q++) acc[mt][nt][q] = 0.f;
    float Lacc = 0.f;
    int lr = tid / 3, lj = tid - (tid / 3) * 3;   // logits assignment (tid<384)

    LOAD_A(0, 0);
    LOAD_B(0, 0, 288);
    CPCOMMIT();

    for (int c = 0; c < 6; c++) {
        int buf = c & 1;
        if (c + 1 < 6) {
            LOAD_A(c + 1, buf ^ 1);
            LOAD_B(c + 1, buf ^ 1, Warr[c + 1]);
            CPCOMMIT();
            CPWAIT(1);
        } else {
            CPWAIT(0);
        }
        __syncthreads();

        const __half* Ab = As + (size_t)buf * 128 * 72;
        const __half* Bb = Bs + (size_t)buf * 288 * 72;
        if (c < 3)      do_chunk<288>(Ab, Bb, acc, wm, wn, gid, tq);
        else if (c < 5) do_chunk<192>(Ab, Bb, acc, wm, wn, gid, tq);
        else            do_chunk<96>(Ab, Bb, acc, wm, wn, gid, tq);

        // logits on the same A chunk (half2 loads, fp32 accumulate)
        if (tid < 384) {
            const __half2* Ar2 = (const __half2*)(Ab + lr * 72);
            const float* A3c = A3s + c * 192 + lj;
#pragma unroll 8
            for (int kk2 = 0; kk2 < 32; kk2++) {
                float2 f = __half22float2(Ar2[kk2]);
                Lacc += f.x * A3c[kk2 * 6] + f.y * A3c[kk2 * 6 + 3];
            }
        }
        __syncthreads();
    }

    // ---- epilogue ----
    if (tid < 384) Ls[tid] = Lacc;
    if (tid < 192) bnS[tid] = 0.f;
#pragma unroll
    for (int mt = 0; mt < 2; mt++) {
        int row = wm * 32 + mt * 16 + gid;
#pragma unroll
        for (int nt = 0; nt < 9; nt++) {
            int cc = wn * 72 + nt * 8 + tq * 2;
            *(float2*)(stage + row * STG_PITCH + cc) = make_float2(acc[mt][nt][0], acc[mt][nt][1]);
            *(float2*)(stage + (row + 8) * STG_PITCH + cc) = make_float2(acc[mt][nt][2], acc[mt][nt][3]);
        }
    }
    __syncthreads();

    if (tid < 128) {
        float l0 = Ls[tid * 3 + 0] + g_lconst[0];
        float l1 = Ls[tid * 3 + 1] + g_lconst[1];
        float l2 = Ls[tid * 3 + 2] + g_lconst[2];
        float m = fmaxf(l0, fmaxf(l1, l2));
        float e0 = __expf(l0 - m), e1 = __expf(l1 - m), e2 = __expf(l2 - m);
        float inv = 1.f / (e0 + e1 + e2);
        Ws[tid * 3 + 0] = e0 * inv;
        Ws[tid * 3 + 1] = e1 * inv;
        Ws[tid * 3 + 2] = e2 * inv;
    }
    __syncthreads();

    if (tid < 384) {
        int c = tid % 96, q = tid / 96;
        // N-block b holds scale 2-b
        float cs0 = g_cs[c], cs1 = g_cs[96 + c], cs2 = g_cs[192 + c];
        float fb = fus_b[c];
        float lsum = 0.f, lsq = 0.f;
        for (int r = q * 32; r < q * 32 + 32; r++) {
            int m = m0 + r;
            if (m >= NN) break;
            float w2s = Ws[r * 3 + 2];   // scale2 -> block 0
            float w1s = Ws[r * 3 + 1];   // scale1 -> block 1
            float w0s = Ws[r * 3 + 0];   // scale0 -> block 2
            const float* f = stage + r * STG_PITCH;
            float h = w2s * (f[c] + cs0) + w1s * (f[96 + c] + cs1) + w0s * (f[192 + c] + cs2) + fb;
            g_h[(size_t)m * C + c] = h;
            lsum += h;
            lsq += h * h;
        }
        atomicAdd(&bnS[c], lsum);
        atomicAdd(&bnS[96 + c], lsq);
    }
    __syncthreads();
    if (tid < 96) {
        atomicAdd(&g_sum[tid], bnS[tid]);
        atomicAdd(&g_sumsq[tid], bnS[96 + tid]);
    }
#undef LOAD_A
#undef LOAD_B
}

// ---------------- BN finalize + normalize (fused) ----------------
__global__ void k_norm(const float* __restrict__ gamma, const float* __restrict__ beta,
                       float* __restrict__ out) {
    __shared__ float sc[C], sh[C];
    int tid = threadIdx.x;
    if (tid < C) {
        float mean = g_sum[tid] / (float)NN;
        float var = g_sumsq[tid] / (float)NN - mean * mean;
        var = fmaxf(var, 0.f);
        float s = gamma[tid] * rsqrtf(var + BN_EPS);
        sc[tid] = s;
        sh[tid] = beta[tid] - mean * s;
    }
    __syncthreads();
    int i = blockIdx.x * blockDim.x + tid;
    if (i >= NN * C) return;
    int c = i % C;
    out[i] = fmaxf(fmaf(g_h[i], sc[c], sh[c]), 0.f);
}

// ---------------- launch ----------------
extern "C" void kernel_launch(void* const* d_in, const int* in_sizes, int n_in,
                              void* d_out, int out_size) {
    const float* x        = (const float*)d_in[0];
    const void* ei        = d_in[1];
    const float* w2       = (const float*)d_in[2];
    const float* b2       = (const float*)d_in[3];
    const float* w3       = (const float*)d_in[4];
    const float* b3       = (const float*)d_in[5];
    const float* w4       = (const float*)d_in[6];
    const float* b4       = (const float*)d_in[7];
    const float* attn_w   = (const float*)d_in[8];
    const float* attn_b   = (const float*)d_in[9];
    const float* fus_w    = (const float*)d_in[10];
    const float* fus_b    = (const float*)d_in[11];
    const float* bn_gamma = (const float*)d_in[12];
    const float* bn_beta  = (const float*)d_in[13];
    float* out = (float*)d_out;

    static int smem_set = 0;
    if (!smem_set) {
        cudaFuncSetAttribute(k_fused, cudaFuncAttributeMaxDynamicSharedMemorySize, FUSED_SMEM);
        smem_set = 1;
    }

    float* T1 = nullptr;
    cudaGetSymbolAddress((void**)&T1, g_T1);

    k_zero<<<(NN * 48 + 255) / 256, 256>>>(x, (const int*)ei);
    k_edges<<<(NE + 255) / 256, 256>>>(ei);
    k_scan_local<<<49, 256>>>();
    k_scan_add<<<(NN + 255) / 256, 256>>>();
    k_scatter<<<(NE + 255) / 256, 256>>>();
    k_precompU<<<37, 256>>>(w2, w3, w4, fus_w, attn_w, b2, b3, b4, attn_b);

    // T1 = P(T0); T2 = 2*P(T1) - T0; T3 = 2*P(T2) - T1
    k_spmm<<<6250, 256>>>(0, nullptr, T1, 96, 1);
    k_spmm<<<6250, 256>>>(192, x, nullptr, 192, 0);
    k_spmm<<<6250, 256>>>(384, T1, nullptr, 288, 0);

    k_fused<<<TILES, 512, FUSED_SMEM>>>(fus_b);

    k_norm<<<(NN * C + 255) / 256, 256>>>(bn_gamma, bn_beta, out);
}

// round 12
// speedup vs baseline: 3.6185x; 1.0473x over previous
#include <cuda_runtime.h>
#include <cuda_fp16.h>
#include <math.h>
#include <stdint.h>

#define NN 50000
#define NE 800000
#define C 96
#define KW 384            // total K = 4*C  (T0|T1|T2|T3)
#define FW 288            // fused GEMM output width = 3*C
#define BN_EPS 1e-5f
#define TILES 391         // ceil(NN/128)

// ---------------- scratch (device globals; no allocation allowed) ----------------
__device__ __half g_Th[(size_t)NN * KW];   // fp16 mirror of T0..T3, row-major [N][384]
__device__ float g_h[NN * C];              // pre-BN output
__device__ float g_deg[NN];
__device__ float g_dis[NN];
__device__ int   g_cnt[NN];
__device__ int   g_ptr[NN + 1];
__device__ int   g_cur[NN];
__device__ int   g_bsum[64];
__device__ int2  g_epair[NE];              // raw (row, col)
__device__ int2  g_epack[NE];              // CSR-ordered (row, bitcast weight)
__device__ int   g_is64;
__device__ float g_A3[KW * 3];
__device__ float g_cs[3 * C];              // reordered: block b = scale 2-b
__device__ float g_lconst[3];
__device__ float g_sum[C];
__device__ float g_sumsq[C];
__device__ __half g_Uf16[FW * KW];         // n-major [288 n][384 k]; N order (s2|s1|s0); zero blocks never written

// ---------------- small helpers ----------------
__device__ __forceinline__ uint32_t smem_u32(const void* p) {
    uint32_t a;
    asm("{ .reg .u64 t; cvta.to.shared.u64 t, %1; cvt.u32.u64 %0, t; }" : "=r"(a) : "l"(p));
    return a;
}
#define CP16(dst, src) asm volatile("cp.async.cg.shared.global [%0], [%1], 16;" :: "r"(dst), "l"(src) : "memory")
#define CPCOMMIT()     asm volatile("cp.async.commit_group;" ::: "memory")
#define CPWAIT(n)      asm volatile("cp.async.wait_group %0;" :: "n"(n) : "memory")

__device__ __forceinline__ void mma16816(float* d, const uint32_t* a, const uint32_t* b) {
    asm volatile(
        "mma.sync.aligned.m16n8k16.row.col.f32.f16.f16.f32 "
        "{%0,%1,%2,%3}, {%4,%5,%6,%7}, {%8,%9}, {%0,%1,%2,%3};"
        : "+f"(d[0]), "+f"(d[1]), "+f"(d[2]), "+f"(d[3])
        : "r"(a[0]), "r"(a[1]), "r"(a[2]), "r"(a[3]), "r"(b[0]), "r"(b[1]));
}

// ---------------- zero + dtype detect + x -> fp16 T0 slice ----------------
__global__ void k_zero(const float* __restrict__ x, const int* __restrict__ ei32) {
    int i = blockIdx.x * blockDim.x + threadIdx.x;
    if (i < NN) { g_deg[i] = 0.f; g_cnt[i] = 0; }
    if (i < KW * 3) g_A3[i] = 0.f;
    if (i < C) { g_sum[i] = 0.f; g_sumsq[i] = 0.f; }
    if (i < NN * 48) {
        int n = i / 48, cp = i - (i / 48) * 48;
        float2 v = *(const float2*)(x + (size_t)n * 96 + cp * 2);
        *(__half2*)(g_Th + (size_t)n * KW + cp * 2) = __floats2half2_rn(v.x, v.y);
    }
    if (blockIdx.x == 0) {
        __shared__ int nz;
        if (threadIdx.x == 0) nz = 0;
        __syncthreads();
        int v = ei32[threadIdx.x * 2 + 1];
        if (v != 0) atomicAdd(&nz, 1);
        __syncthreads();
        if (threadIdx.x == 0) g_is64 = (nz == 0) ? 1 : 0;
    }
}

// ---------------- unpack edges + degree histogram (fused) ----------------
__global__ void k_edges(const void* __restrict__ ei) {
    int e = blockIdx.x * blockDim.x + threadIdx.x;
    if (e >= NE) return;
    int r, c;
    if (g_is64) {
        const long long* p = (const long long*)ei;
        r = (int)p[e];
        c = (int)p[NE + e];
    } else {
        const int* p = (const int*)ei;
        r = p[e];
        c = p[NE + e];
    }
    if ((unsigned)r >= NN) r = 0;
    if ((unsigned)c >= NN) c = 0;
    g_epair[e] = make_int2(r, c);
    atomicAdd(&g_deg[r], 1.0f);
    atomicAdd(&g_cnt[c], 1);
}

// ---------------- exclusive scan of g_cnt -> g_ptr  (+ dis computation) ----------------
__global__ void k_scan_local() {
    __shared__ int wsum[8];
    int t = threadIdx.x;
    int base = blockIdx.x * 1024 + t * 4;
    int v[4];
#pragma unroll
    for (int j = 0; j < 4; j++) {
        int idx = base + j;
        v[j] = (idx < NN) ? g_cnt[idx] : 0;
        if (idx < NN) {
            float d = g_deg[idx];
            g_dis[idx] = (d > 0.f) ? rsqrtf(d) : 0.f;
        }
    }
    int tsum = v[0] + v[1] + v[2] + v[3];
    int lane = t & 31, wid = t >> 5;
    int x = tsum;
#pragma unroll
    for (int o = 1; o < 32; o <<= 1) {
        int y = __shfl_up_sync(0xffffffffu, x, o);
        if (lane >= o) x += y;
    }
    if (lane == 31) wsum[wid] = x;
    __syncthreads();
    if (wid == 0) {
        int wv = (lane < 8) ? wsum[lane] : 0;
#pragma unroll
        for (int o = 1; o < 8; o <<= 1) {
            int y = __shfl_up_sync(0xffffffffu, wv, o);
            if (lane >= o) wv += y;
        }
        if (lane < 8) wsum[lane] = wv;
    }
    __syncthreads();
    int exc = x - tsum + ((wid > 0) ? wsum[wid - 1] : 0);
    int run = exc;
#pragma unroll
    for (int j = 0; j < 4; j++) {
        int idx = base + j;
        if (idx < NN) g_ptr[idx] = run;
        run += v[j];
    }
    if (t == 255) g_bsum[blockIdx.x] = run;
}

__global__ void k_scan_add() {
    __shared__ int accs;
    int i = blockIdx.x * blockDim.x + threadIdx.x;
    if (threadIdx.x == 0) {
        int b = (blockIdx.x * blockDim.x) >> 10;
        int a = 0;
        for (int t = 0; t < b; t++) a += g_bsum[t];
        accs = a;
    }
    __syncthreads();
    if (i < NN) {
        int p = g_ptr[i] + accs;
        g_ptr[i] = p;
        g_cur[i] = p;
    }
    if (i == 0) g_ptr[NN] = NE;
}

__global__ void k_scatter() {
    int e = blockIdx.x * blockDim.x + threadIdx.x;
    if (e >= NE) return;
    int2 p = g_epair[e];
    int pos = atomicAdd(&g_cur[p.y], 1);
    g_epack[pos] = make_int2(p.x, __float_as_int(-(g_dis[p.x] * g_dis[p.y])));
}

// ---------------- precompute combined weights (parallelized: 36 + 1 blocks) ----------------
// N-order reversed: scale s lives in block (2-s).
__global__ void k_precompU(const float* __restrict__ w2, const float* __restrict__ w3,
                           const float* __restrict__ w4, const float* __restrict__ fus_w,
                           const float* __restrict__ attn_w,
                           const float* __restrict__ b2, const float* __restrict__ b3,
                           const float* __restrict__ b4, const float* __restrict__ attn_b) {
    int b = blockIdx.x;
    if (b == 36) {
        for (int t = threadIdx.x; t < 3 * C; t += blockDim.x) {
            int s = t / C, j = t - s * C;
            const float* bs = (s == 0) ? b2 : (s == 1) ? b3 : b4;
            float acc = 0.f;
            for (int m = 0; m < C; m++) acc += bs[m] * fus_w[(s * C + m) * C + j];
            g_cs[(2 - s) * C + j] = acc;
        }
        if (threadIdx.x < 3) {
            int t = threadIdx.x;
            float acc = attn_b[t];
            for (int s = 0; s < 3; s++) {
                const float* bs = (s == 0) ? b2 : (s == 1) ? b3 : b4;
                for (int m = 0; m < C; m++) acc += bs[m] * attn_w[(s * C + m) * 3 + t];
            }
            g_lconst[t] = acc;
        }
        return;
    }
    const int Ss[9] = {0, 0, 1, 1, 1, 2, 2, 2, 2};
    const int Kk[9] = {0, 1, 0, 1, 2, 0, 1, 2, 3};
    int wb = b >> 2, qr = b & 3;          // weight-block, row-quarter
    int s = Ss[wb], k = Kk[wb];
    const float* w = ((s == 0) ? w2 : (s == 1) ? w3 : w4) + k * C * C;
    __shared__ float fusS[C * C];
    for (int i = threadIdx.x; i < C * C; i += blockDim.x)
        fusS[i] = fus_w[s * C * C + i];
    __syncthreads();
    for (int id = threadIdx.x; id < 24 * C; id += blockDim.x) {
        int i = qr * 24 + id / C, j = id % C;
        float acc = 0.f;
#pragma unroll 8
        for (int m = 0; m < C; m++) acc += w[i * C + m] * fusS[m * C + j];
        g_Uf16[(size_t)((2 - s) * C + j) * KW + (k * C + i)] = __float2half(acc);
    }
    for (int id = threadIdx.x; id < 24 * 3; id += blockDim.x) {
        int i = qr * 24 + id / 3, j = id % 3;
        float acc = 0.f;
#pragma unroll 8
        for (int m = 0; m < C; m++) acc += w[i * C + m] * attn_w[(s * C + m) * 3 + j];
        atomicAdd(&g_A3[(k * C + i) * 3 + j], acc);
    }
}

// ---------------- SpMM: warp per node, 2 edges/LDG.128, depth-2 software pipeline ----------------
#define SPMM_ACC(vv, ww)                                                                    \
    {                                                                                       \
        const __half2* hp = (const __half2*)&(vv);                                          \
        _Pragma("unroll") for (int q = 0; q < 4; q++) {                                     \
            float2 f = __half22float2(hp[q]);                                               \
            acc[2 * q]     += (ww) * f.x;                                                   \
            acc[2 * q + 1] += (ww) * f.y;                                                   \
        }                                                                                   \
    }

// sub_byte_off < 0 -> first pass (no subtraction); else subtraction term read from g_Th slice.
__global__ void k_spmm(int in_byte_off, int sub_byte_off, int out_byte_off, int first) {
    int warp = (blockIdx.x * blockDim.x + threadIdx.x) >> 5;
    int lane = threadIdx.x & 31;
    if (warp >= NN) return;
    int s = g_ptr[warp], e = g_ptr[warp + 1];
    bool act = lane < 24;
    int gl = lane % 12;       // which uint4 of the 192B slice
    int gsel = lane / 12;     // which edge of the pair
    float acc[8];
#pragma unroll
    for (int q = 0; q < 8; q++) acc[q] = 0.f;
    const char* base = (const char*)g_Th + in_byte_off + gl * 16;

    int i = s;
    int2 p0 = make_int2(0, 0), p1 = make_int2(0, 0);
    uint4 v0 = make_uint4(0, 0, 0, 0);
    if (act && i + 1 < e) {
        p0 = g_epack[i + gsel];
        v0 = *(const uint4*)(base + (size_t)p0.x * 768);
    }
    if (act && i + 3 < e) p1 = g_epack[i + 2 + gsel];
    for (; i + 3 < e; i += 2) {
        uint4 v1;
        int2 p2 = p1;
        if (act) {
            v1 = *(const uint4*)(base + (size_t)p1.x * 768);
            if (i + 5 < e) p2 = g_epack[i + 4 + gsel];
            SPMM_ACC(v0, __int_as_float(p0.y));
            p0 = p1; v0 = v1; p1 = p2;
        }
    }
    if (i + 1 < e) {
        if (act) SPMM_ACC(v0, __int_as_float(p0.y));
        i += 2;
    }
    if (i < e && lane < 12) {
        int2 p = g_epack[i];
        uint4 v = *(const uint4*)(base + (size_t)p.x * 768);
        SPMM_ACC(v, __int_as_float(p.y));
    }
    // fold group 1 (lanes 12-23) into group 0 (lanes 0-11)
#pragma unroll
    for (int q = 0; q < 8; q++) {
        float o = __shfl_down_sync(0xffffffffu, acc[q], 12);
        acc[q] += o;
    }
    if (lane < 12) {
        if (!first) {
            uint4 sv = *(const uint4*)((const char*)g_Th + (size_t)warp * 768 + sub_byte_off + gl * 16);
            const __half2* sp = (const __half2*)&sv;
#pragma unroll
            for (int q = 0; q < 4; q++) {
                float2 f = __half22float2(sp[q]);
                acc[2 * q]     = 2.f * acc[2 * q] - f.x;
                acc[2 * q + 1] = 2.f * acc[2 * q + 1] - f.y;
            }
        }
        __half2 h[4];
#pragma unroll
        for (int q = 0; q < 4; q++) h[q] = __floats2half2_rn(acc[2 * q], acc[2 * q + 1]);
        *(uint4*)((char*)g_Th + (size_t)warp * 768 + out_byte_off + gl * 16) = *(const uint4*)h;
    }
}

// ---------------- fused GEMM + logits + softmax combine + BN partials ----------------
// CTA tile 128(M) x 288(N), 512 threads = 16 warps (4m x 4n), warp tile 32x72.
// K = 6 chunks of 64; per-chunk active N-width W = {288,288,288,192,192,96}.
#define SM_A_BYTES (2 * 128 * 72 * 2)                       // 36864
#define SM_B_OFF SM_A_BYTES
#define SM_B_BYTES (2 * 288 * 72 * 2)                       // 82944
#define STG_PITCH 292
#define SM_A3_OFF (128 * STG_PITCH * 4)                     // 149504 (above stage)
#define SM_LS_OFF (SM_A3_OFF + KW * 3 * 4)                  // 154112
#define SM_WS_OFF (SM_LS_OFF + 128 * 3 * 4)                 // 155648
#define FUSED_SMEM (SM_WS_OFF + 128 * 3 * 4)                // 157184

template <int WC>
__device__ __forceinline__ void do_chunk(const __half* __restrict__ Ab,
                                         const __half* __restrict__ Bb,
                                         float (&acc)[2][9][4],
                                         int wm, int wn, int gid, int tq) {
    if (WC < 288 && wn * 72 >= WC) return;
#pragma unroll
    for (int k16 = 0; k16 < 4; k16++) {
        int kk = k16 * 16 + tq * 2;
        uint32_t afr[2][4];
#pragma unroll
        for (int mt = 0; mt < 2; mt++) {
            int r = wm * 32 + mt * 16 + gid;
            afr[mt][0] = *(const uint32_t*)(Ab + r * 72 + kk);
            afr[mt][1] = *(const uint32_t*)(Ab + (r + 8) * 72 + kk);
            afr[mt][2] = *(const uint32_t*)(Ab + r * 72 + kk + 8);
            afr[mt][3] = *(const uint32_t*)(Ab + (r + 8) * 72 + kk + 8);
        }
#pragma unroll
        for (int nt = 0; nt < 9; nt++) {
            if (WC < 288 && wn * 72 + nt * 8 >= WC) break;
            int n = wn * 72 + nt * 8 + gid;
            uint32_t bfr[2];
            bfr[0] = *(const uint32_t*)(Bb + n * 72 + kk);
            bfr[1] = *(const uint32_t*)(Bb + n * 72 + kk + 8);
            mma16816(acc[0][nt], afr[0], bfr);
            mma16816(acc[1][nt], afr[1], bfr);
        }
    }
}

__global__ void __launch_bounds__(512, 1) k_fused(const float* __restrict__ fus_b) {
    extern __shared__ unsigned char dyn[];
    __half* As = (__half*)dyn;                    // [2][128][72]
    __half* Bs = (__half*)(dyn + SM_B_OFF);       // [2][288][72]
    float* A3s = (float*)(dyn + SM_A3_OFF);       // [384][3]
    float* Ls = (float*)(dyn + SM_LS_OFF);        // [128][3]
    float* Ws = (float*)(dyn + SM_WS_OFF);        // [128][3]
    float* stage = (float*)dyn;                   // [128][292] (epilogue, overlaps A/B)
    float* bnS = A3s;                             // [192] (epilogue, overlaps A3s)
    uint32_t smA = smem_u32(As);
    uint32_t smB = smem_u32(Bs);

    int tid = threadIdx.x;
    int lane = tid & 31, wid = tid >> 5;
    int wm = wid & 3, wn = wid >> 2;
    int gid = lane >> 2, tq = lane & 3;
    int m0 = blockIdx.x * 128;

    for (int i = tid; i < KW * 3; i += 512) A3s[i] = g_A3[i];

    const int Warr[6] = {288, 288, 288, 192, 192, 96};

#define LOAD_A(chunk, buf)                                                                  \
    {                                                                                       \
        _Pragma("unroll") for (int i = 0; i < 2; i++) {                                     \
            int idx = tid + i * 512;                                                        \
            int row = idx >> 3, seg = idx & 7;                                              \
            int srow = m0 + row; if (srow >= NN) srow = NN - 1;                             \
            const __half* src = g_Th + (size_t)srow * KW + (chunk) * 64 + seg * 8;          \
            uint32_t dst = smA + (((buf) * 128 + row) * 72 + seg * 8) * 2;                  \
            CP16(dst, src);                                                                 \
        }                                                                                   \
    }
#define LOAD_B(chunk, buf, wb)                                                              \
    {                                                                                       \
        _Pragma("unroll") for (int i = 0; i < 5; i++) {                                     \
            int idx = tid + i * 512;                                                        \
            int row = idx >> 3, seg = idx & 7;                                              \
            if (row < (wb)) {                                                               \
                const __half* src = g_Uf16 + (size_t)row * KW + (chunk) * 64 + seg * 8;     \
                uint32_t dst = smB + (((buf) * 288 + row) * 72 + seg * 8) * 2;              \
                CP16(dst, src);                                                             \
            }                                                                               \
        }                                                                                   \
    }

    float acc[2][9][4];
#pragma unroll
    for (int mt = 0; mt < 2; mt++)
#pragma unroll
        for (int nt = 0; nt < 9; nt++)
#pragma unroll
            for (int q = 0; q < 4; q++) acc[mt][nt][q] = 0.f;
    float Lacc = 0.f;
    int lr = tid / 3, lj = tid - (tid / 3) * 3;   // logits assignment (tid<384)

    LOAD_A(0, 0);
    LOAD_B(0, 0, 288);
    CPCOMMIT();

    for (int c = 0; c < 6; c++) {
        int buf = c & 1;
        if (c + 1 < 6) {
            LOAD_A(c + 1, buf ^ 1);
            LOAD_B(c + 1, buf ^ 1, Warr[c + 1]);
            CPCOMMIT();
            CPWAIT(1);
        } else {
            CPWAIT(0);
        }
        __syncthreads();

        const __half* Ab = As + (size_t)buf * 128 * 72;
        const __half* Bb = Bs + (size_t)buf * 288 * 72;
        if (c < 3)      do_chunk<288>(Ab, Bb, acc, wm, wn, gid, tq);
        else if (c < 5) do_chunk<192>(Ab, Bb, acc, wm, wn, gid, tq);
        else            do_chunk<96>(Ab, Bb, acc, wm, wn, gid, tq);

        // logits on the same A chunk (half2 loads, fp32 accumulate)
        if (tid < 384) {
            const __half2* Ar2 = (const __half2*)(Ab + lr * 72);
            const float* A3c = A3s + c * 192 + lj;
#pragma unroll 8
            for (int kk2 = 0; kk2 < 32; kk2++) {
                float2 f = __half22float2(Ar2[kk2]);
                Lacc += f.x * A3c[kk2 * 6] + f.y * A3c[kk2 * 6 + 3];
            }
        }
        __syncthreads();
    }

    // ---- epilogue ----
    if (tid < 384) Ls[tid] = Lacc;
    if (tid < 192) bnS[tid] = 0.f;
#pragma unroll
    for (int mt = 0; mt < 2; mt++) {
        int row = wm * 32 + mt * 16 + gid;
#pragma unroll
        for (int nt = 0; nt < 9; nt++) {
            int cc = wn * 72 + nt * 8 + tq * 2;
            *(float2*)(stage + row * STG_PITCH + cc) = make_float2(acc[mt][nt][0], acc[mt][nt][1]);
            *(float2*)(stage + (row + 8) * STG_PITCH + cc) = make_float2(acc[mt][nt][2], acc[mt][nt][3]);
        }
    }
    __syncthreads();

    if (tid < 128) {
        float l0 = Ls[tid * 3 + 0] + g_lconst[0];
        float l1 = Ls[tid * 3 + 1] + g_lconst[1];
        float l2 = Ls[tid * 3 + 2] + g_lconst[2];
        float m = fmaxf(l0, fmaxf(l1, l2));
        float e0 = __expf(l0 - m), e1 = __expf(l1 - m), e2 = __expf(l2 - m);
        float inv = 1.f / (e0 + e1 + e2);
        Ws[tid * 3 + 0] = e0 * inv;
        Ws[tid * 3 + 1] = e1 * inv;
        Ws[tid * 3 + 2] = e2 * inv;
    }
    __syncthreads();

    if (tid < 384) {
        int c = tid % 96, q = tid / 96;
        // N-block b holds scale 2-b
        float cs0 = g_cs[c], cs1 = g_cs[96 + c], cs2 = g_cs[192 + c];
        float fb = fus_b[c];
        float lsum = 0.f, lsq = 0.f;
        for (int r = q * 32; r < q * 32 + 32; r++) {
            int m = m0 + r;
            if (m >= NN) break;
            float w2s = Ws[r * 3 + 2];   // scale2 -> block 0
            float w1s = Ws[r * 3 + 1];   // scale1 -> block 1
            float w0s = Ws[r * 3 + 0];   // scale0 -> block 2
            const float* f = stage + r * STG_PITCH;
            float h = w2s * (f[c] + cs0) + w1s * (f[96 + c] + cs1) + w0s * (f[192 + c] + cs2) + fb;
            g_h[(size_t)m * C + c] = h;
            lsum += h;
            lsq += h * h;
        }
        atomicAdd(&bnS[c], lsum);
        atomicAdd(&bnS[96 + c], lsq);
    }
    __syncthreads();
    if (tid < 96) {
        atomicAdd(&g_sum[tid], bnS[tid]);
        atomicAdd(&g_sumsq[tid], bnS[96 + tid]);
    }
#undef LOAD_A
#undef LOAD_B
}

// ---------------- BN finalize + normalize (fused) ----------------
__global__ void k_norm(const float* __restrict__ gamma, const float* __restrict__ beta,
                       float* __restrict__ out) {
    __shared__ float sc[C], sh[C];
    int tid = threadIdx.x;
    if (tid < C) {
        float mean = g_sum[tid] / (float)NN;
        float var = g_sumsq[tid] / (float)NN - mean * mean;
        var = fmaxf(var, 0.f);
        float s = gamma[tid] * rsqrtf(var + BN_EPS);
        sc[tid] = s;
        sh[tid] = beta[tid] - mean * s;
    }
    __syncthreads();
    int i = blockIdx.x * blockDim.x + tid;
    if (i >= NN * C) return;
    int c = i % C;
    out[i] = fmaxf(fmaf(g_h[i], sc[c], sh[c]), 0.f);
}

// ---------------- launch ----------------
extern "C" void kernel_launch(void* const* d_in, const int* in_sizes, int n_in,
                              void* d_out, int out_size) {
    const float* x        = (const float*)d_in[0];
    const void* ei        = d_in[1];
    const float* w2       = (const float*)d_in[2];
    const float* b2       = (const float*)d_in[3];
    const float* w3       = (const float*)d_in[4];
    const float* b3       = (const float*)d_in[5];
    const float* w4       = (const float*)d_in[6];
    const float* b4       = (const float*)d_in[7];
    const float* attn_w   = (const float*)d_in[8];
    const float* attn_b   = (const float*)d_in[9];
    const float* fus_w    = (const float*)d_in[10];
    const float* fus_b    = (const float*)d_in[11];
    const float* bn_gamma = (const float*)d_in[12];
    const float* bn_beta  = (const float*)d_in[13];
    float* out = (float*)d_out;

    static int smem_set = 0;
    if (!smem_set) {
        cudaFuncSetAttribute(k_fused, cudaFuncAttributeMaxDynamicSharedMemorySize, FUSED_SMEM);
        smem_set = 1;
    }

    k_zero<<<(NN * 48 + 255) / 256, 256>>>(x, (const int*)ei);
    k_edges<<<(NE + 255) / 256, 256>>>(ei);
    k_scan_local<<<49, 256>>>();
    k_scan_add<<<(NN + 255) / 256, 256>>>();
    k_scatter<<<(NE + 255) / 256, 256>>>();
    k_precompU<<<37, 256>>>(w2, w3, w4, fus_w, attn_w, b2, b3, b4, attn_b);

    // T1 = P(T0); T2 = 2*P(T1) - T0; T3 = 2*P(T2) - T1   (byte offsets into g_Th rows)
    k_spmm<<<6250, 256>>>(0, -1, 192, 1);
    k_spmm<<<6250, 256>>>(192, 0, 384, 0);
    k_spmm<<<6250, 256>>>(384, 192, 576, 0);

    k_fused<<<TILES, 512, FUSED_SMEM>>>(fus_b);

    k_norm<<<(NN * C + 255) / 256, 256>>>(bn_gamma, bn_beta, out);
}

// round 13
// speedup vs baseline: 3.8464x; 1.0630x over previous
#include <cuda_runtime.h>
#include <cuda_fp16.h>
#include <math.h>
#include <stdint.h>

#define NN 50000
#define NE 800000
#define C 96
#define KW 384            // total K = 4*C  (T0|T1|T2|T3)
#define FW 288            // fused GEMM output width = 3*C
#define BN_EPS 1e-5f
#define TILES 391         // ceil(NN/128)

// ---------------- scratch (device globals; no allocation allowed) ----------------
__device__ __half g_Th[(size_t)NN * KW];   // fp16 mirror of T0..T3, row-major [N][384]
__device__ float g_h[NN * C];              // pre-BN output
__device__ float g_deg[NN];                // zeroed at end of k_norm (module-load zero initially)
__device__ float g_dis[NN];
__device__ int   g_cnt[NN];                // zeroed at end of k_norm
__device__ int   g_ptr[NN + 1];
__device__ int   g_cur[NN];
__device__ int   g_bsum[64];
__device__ int2  g_epair[NE];              // raw (row, col)
__device__ int2  g_epack[NE];              // CSR-ordered (row, bitcast weight)
__device__ float g_A3[KW * 3];             // zeroed in k_scatter (before precompU writes)
__device__ float g_cs[3 * C];              // reordered: block b = scale 2-b
__device__ float g_lconst[3];
__device__ float g_sum[C];                 // zeroed in k_scatter (before k_fused writes)
__device__ float g_sumsq[C];
__device__ __half g_Uf16[FW * KW];         // n-major [288 n][384 k]; N order (s2|s1|s0); zero blocks never written

// ---------------- small helpers ----------------
__device__ __forceinline__ uint32_t smem_u32(const void* p) {
    uint32_t a;
    asm("{ .reg .u64 t; cvta.to.shared.u64 t, %1; cvt.u32.u64 %0, t; }" : "=r"(a) : "l"(p));
    return a;
}
#define CP16(dst, src) asm volatile("cp.async.cg.shared.global [%0], [%1], 16;" :: "r"(dst), "l"(src) : "memory")
#define CPCOMMIT()     asm volatile("cp.async.commit_group;" ::: "memory")
#define CPWAIT(n)      asm volatile("cp.async.wait_group %0;" :: "n"(n) : "memory")

__device__ __forceinline__ void mma16816(float* d, const uint32_t* a, const uint32_t* b) {
    asm volatile(
        "mma.sync.aligned.m16n8k16.row.col.f32.f16.f16.f32 "
        "{%0,%1,%2,%3}, {%4,%5,%6,%7}, {%8,%9}, {%0,%1,%2,%3};"
        : "+f"(d[0]), "+f"(d[1]), "+f"(d[2]), "+f"(d[3])
        : "r"(a[0]), "r"(a[1]), "r"(a[2]), "r"(a[3]), "r"(b[0]), "r"(b[1]));
}

// ---------------- edges: dtype detect (per block) + x->fp16 T0 + unpack + histograms ----------------
__global__ void k_edges(const void* __restrict__ ei, const float* __restrict__ x) {
    // per-block dtype detection: int64 edge_index has zero odd 32-bit words
    const int* w = (const int*)ei;
    int v = w[(threadIdx.x & 255) * 2 + 1];
    int any = __syncthreads_or(v != 0);
    int is64 = !any;

    int i = blockIdx.x * blockDim.x + threadIdx.x;

    // x -> fp16 T0 slice (4 channels per thread)
    if (i < NN * 24) {
        int n = i / 24, cp = i - (i / 24) * 24;
        float4 vx = *(const float4*)(x + (size_t)n * 96 + cp * 4);
        __half2* dst = (__half2*)(g_Th + (size_t)n * KW + cp * 4);
        dst[0] = __floats2half2_rn(vx.x, vx.y);
        dst[1] = __floats2half2_rn(vx.z, vx.w);
    }

    // edge unpack + degree histograms
    if (i < NE) {
        int r, c;
        if (is64) {
            const long long* p = (const long long*)ei;
            r = (int)p[i];
            c = (int)p[NE + i];
        } else {
            const int* p = (const int*)ei;
            r = p[i];
            c = p[NE + i];
        }
        if ((unsigned)r >= NN) r = 0;
        if ((unsigned)c >= NN) c = 0;
        g_epair[i] = make_int2(r, c);
        atomicAdd(&g_deg[r], 1.0f);
        atomicAdd(&g_cnt[c], 1);
    }
}

// ---------------- exclusive scan of g_cnt -> g_ptr  (+ dis computation) ----------------
__global__ void k_scan_local() {
    __shared__ int wsum[8];
    int t = threadIdx.x;
    int base = blockIdx.x * 1024 + t * 4;
    int v[4];
#pragma unroll
    for (int j = 0; j < 4; j++) {
        int idx = base + j;
        v[j] = (idx < NN) ? g_cnt[idx] : 0;
        if (idx < NN) {
            float d = g_deg[idx];
            g_dis[idx] = (d > 0.f) ? rsqrtf(d) : 0.f;
        }
    }
    int tsum = v[0] + v[1] + v[2] + v[3];
    int lane = t & 31, wid = t >> 5;
    int x = tsum;
#pragma unroll
    for (int o = 1; o < 32; o <<= 1) {
        int y = __shfl_up_sync(0xffffffffu, x, o);
        if (lane >= o) x += y;
    }
    if (lane == 31) wsum[wid] = x;
    __syncthreads();
    if (wid == 0) {
        int wv = (lane < 8) ? wsum[lane] : 0;
#pragma unroll
        for (int o = 1; o < 8; o <<= 1) {
            int y = __shfl_up_sync(0xffffffffu, wv, o);
            if (lane >= o) wv += y;
        }
        if (lane < 8) wsum[lane] = wv;
    }
    __syncthreads();
    int exc = x - tsum + ((wid > 0) ? wsum[wid - 1] : 0);
    int run = exc;
#pragma unroll
    for (int j = 0; j < 4; j++) {
        int idx = base + j;
        if (idx < NN) g_ptr[idx] = run;
        run += v[j];
    }
    if (t == 255) g_bsum[blockIdx.x] = run;
}

__global__ void k_scan_add() {
    __shared__ int sb[64];
    __shared__ int accs;
    int t = threadIdx.x;
    if (t < 49) sb[t] = g_bsum[t];
    __syncthreads();
    if (t == 0) {
        int b = (blockIdx.x * blockDim.x) >> 10;
        int a = 0;
        for (int k = 0; k < b; k++) a += sb[k];
        accs = a;
    }
    __syncthreads();
    int i = blockIdx.x * blockDim.x + t;
    if (i < NN) {
        int p = g_ptr[i] + accs;
        g_ptr[i] = p;
        g_cur[i] = p;
    }
    if (i == 0) g_ptr[NN] = NE;
}

// ---------------- scatter into CSR + zero accumulators for downstream kernels ----------------
__global__ void k_scatter() {
    int e = blockIdx.x * blockDim.x + threadIdx.x;
    if (e < KW * 3) g_A3[e] = 0.f;
    if (e < C) { g_sum[e] = 0.f; g_sumsq[e] = 0.f; }
    if (e >= NE) return;
    int2 p = g_epair[e];
    int pos = atomicAdd(&g_cur[p.y], 1);
    g_epack[pos] = make_int2(p.x, __float_as_int(-(g_dis[p.x] * g_dis[p.y])));
}

// ---------------- precompute combined weights (parallelized: 36 + 1 blocks) ----------------
// N-order reversed: scale s lives in block (2-s).
__global__ void k_precompU(const float* __restrict__ w2, const float* __restrict__ w3,
                           const float* __restrict__ w4, const float* __restrict__ fus_w,
                           const float* __restrict__ attn_w,
                           const float* __restrict__ b2, const float* __restrict__ b3,
                           const float* __restrict__ b4, const float* __restrict__ attn_b) {
    int b = blockIdx.x;
    if (b == 36) {
        for (int t = threadIdx.x; t < 3 * C; t += blockDim.x) {
            int s = t / C, j = t - s * C;
            const float* bs = (s == 0) ? b2 : (s == 1) ? b3 : b4;
            float acc = 0.f;
            for (int m = 0; m < C; m++) acc += bs[m] * fus_w[(s * C + m) * C + j];
            g_cs[(2 - s) * C + j] = acc;
        }
        if (threadIdx.x < 3) {
            int t = threadIdx.x;
            float acc = attn_b[t];
            for (int s = 0; s < 3; s++) {
                const float* bs = (s == 0) ? b2 : (s == 1) ? b3 : b4;
                for (int m = 0; m < C; m++) acc += bs[m] * attn_w[(s * C + m) * 3 + t];
            }
            g_lconst[t] = acc;
        }
        return;
    }
    const int Ss[9] = {0, 0, 1, 1, 1, 2, 2, 2, 2};
    const int Kk[9] = {0, 1, 0, 1, 2, 0, 1, 2, 3};
    int wb = b >> 2, qr = b & 3;          // weight-block, row-quarter
    int s = Ss[wb], k = Kk[wb];
    const float* w = ((s == 0) ? w2 : (s == 1) ? w3 : w4) + k * C * C;
    __shared__ float fusS[C * C];
    for (int i = threadIdx.x; i < C * C; i += blockDim.x)
        fusS[i] = fus_w[s * C * C + i];
    __syncthreads();
    for (int id = threadIdx.x; id < 24 * C; id += blockDim.x) {
        int i = qr * 24 + id / C, j = id % C;
        float acc = 0.f;
#pragma unroll 8
        for (int m = 0; m < C; m++) acc += w[i * C + m] * fusS[m * C + j];
        g_Uf16[(size_t)((2 - s) * C + j) * KW + (k * C + i)] = __float2half(acc);
    }
    for (int id = threadIdx.x; id < 24 * 3; id += blockDim.x) {
        int i = qr * 24 + id / 3, j = id % 3;
        float acc = 0.f;
#pragma unroll 8
        for (int m = 0; m < C; m++) acc += w[i * C + m] * attn_w[(s * C + m) * 3 + j];
        atomicAdd(&g_A3[(k * C + i) * 3 + j], acc);
    }
}

// ---------------- SpMM: warp per node, 2 edges/LDG.128, depth-2 software pipeline ----------------
#define SPMM_ACC(vv, ww)                                                                    \
    {                                                                                       \
        const __half2* hp = (const __half2*)&(vv);                                          \
        _Pragma("unroll") for (int q = 0; q < 4; q++) {                                     \
            float2 f = __half22float2(hp[q]);                                               \
            acc[2 * q]     += (ww) * f.x;                                                   \
            acc[2 * q + 1] += (ww) * f.y;                                                   \
        }                                                                                   \
    }

// sub_byte_off < 0 -> first pass (no subtraction); else subtraction term read from g_Th slice.
__global__ void k_spmm(int in_byte_off, int sub_byte_off, int out_byte_off, int first) {
    int warp = (blockIdx.x * blockDim.x + threadIdx.x) >> 5;
    int lane = threadIdx.x & 31;
    if (warp >= NN) return;
    int s = g_ptr[warp], e = g_ptr[warp + 1];
    bool act = lane < 24;
    int gl = lane % 12;       // which uint4 of the 192B slice
    int gsel = lane / 12;     // which edge of the pair
    float acc[8];
#pragma unroll
    for (int q = 0; q < 8; q++) acc[q] = 0.f;
    const char* base = (const char*)g_Th + in_byte_off + gl * 16;

    int i = s;
    int2 p0 = make_int2(0, 0), p1 = make_int2(0, 0);
    uint4 v0 = make_uint4(0, 0, 0, 0);
    if (act && i + 1 < e) {
        p0 = g_epack[i + gsel];
        v0 = *(const uint4*)(base + (size_t)p0.x * 768);
    }
    if (act && i + 3 < e) p1 = g_epack[i + 2 + gsel];
    for (; i + 3 < e; i += 2) {
        uint4 v1;
        int2 p2 = p1;
        if (act) {
            v1 = *(const uint4*)(base + (size_t)p1.x * 768);
            if (i + 5 < e) p2 = g_epack[i + 4 + gsel];
            SPMM_ACC(v0, __int_as_float(p0.y));
            p0 = p1; v0 = v1; p1 = p2;
        }
    }
    if (i + 1 < e) {
        if (act) SPMM_ACC(v0, __int_as_float(p0.y));
        i += 2;
    }
    if (i < e && lane < 12) {
        int2 p = g_epack[i];
        uint4 v = *(const uint4*)(base + (size_t)p.x * 768);
        SPMM_ACC(v, __int_as_float(p.y));
    }
    // fold group 1 (lanes 12-23) into group 0 (lanes 0-11)
#pragma unroll
    for (int q = 0; q < 8; q++) {
        float o = __shfl_down_sync(0xffffffffu, acc[q], 12);
        acc[q] += o;
    }
    if (lane < 12) {
        if (!first) {
            uint4 sv = *(const uint4*)((const char*)g_Th + (size_t)warp * 768 + sub_byte_off + gl * 16);
            const __half2* sp = (const __half2*)&sv;
#pragma unroll
            for (int q = 0; q < 4; q++) {
                float2 f = __half22float2(sp[q]);
                acc[2 * q]     = 2.f * acc[2 * q] - f.x;
                acc[2 * q + 1] = 2.f * acc[2 * q + 1] - f.y;
            }
        }
        __half2 h[4];
#pragma unroll
        for (int q = 0; q < 4; q++) h[q] = __floats2half2_rn(acc[2 * q], acc[2 * q + 1]);
        *(uint4*)((char*)g_Th + (size_t)warp * 768 + out_byte_off + gl * 16) = *(const uint4*)h;
    }
}

// ---------------- fused GEMM + logits + softmax combine + BN partials ----------------
// CTA tile 128(M) x 288(N), 512 threads = 16 warps (4m x 4n), warp tile 32x72.
// K = 6 chunks of 64; per-chunk active N-width W = {288,288,288,192,192,96}.
#define SM_A_BYTES (2 * 128 * 72 * 2)                       // 36864
#define SM_B_OFF SM_A_BYTES
#define SM_B_BYTES (2 * 288 * 72 * 2)                       // 82944
#define STG_PITCH 292
#define SM_A3_OFF (128 * STG_PITCH * 4)                     // 149504 (above stage)
#define SM_LS_OFF (SM_A3_OFF + KW * 3 * 4)                  // 154112
#define SM_WS_OFF (SM_LS_OFF + 128 * 3 * 4)                 // 155648
#define FUSED_SMEM (SM_WS_OFF + 128 * 3 * 4)                // 157184

template <int WC>
__device__ __forceinline__ void do_chunk(const __half* __restrict__ Ab,
                                         const __half* __restrict__ Bb,
                                         float (&acc)[2][9][4],
                                         int wm, int wn, int gid, int tq) {
    if (WC < 288 && wn * 72 >= WC) return;
#pragma unroll
    for (int k16 = 0; k16 < 4; k16++) {
        int kk = k16 * 16 + tq * 2;
        uint32_t afr[2][4];
#pragma unroll
        for (int mt = 0; mt < 2; mt++) {
            int r = wm * 32 + mt * 16 + gid;
            afr[mt][0] = *(const uint32_t*)(Ab + r * 72 + kk);
            afr[mt][1] = *(const uint32_t*)(Ab + (r + 8) * 72 + kk);
            afr[mt][2] = *(const uint32_t*)(Ab + r * 72 + kk + 8);
            afr[mt][3] = *(const uint32_t*)(Ab + (r + 8) * 72 + kk + 8);
        }
#pragma unroll
        for (int nt = 0; nt < 9; nt++) {
            if (WC < 288 && wn * 72 + nt * 8 >= WC) break;
            int n = wn * 72 + nt * 8 + gid;
            uint32_t bfr[2];
            bfr[0] = *(const uint32_t*)(Bb + n * 72 + kk);
            bfr[1] = *(const uint32_t*)(Bb + n * 72 + kk + 8);
            mma16816(acc[0][nt], afr[0], bfr);
            mma16816(acc[1][nt], afr[1], bfr);
        }
    }
}

__global__ void __launch_bounds__(512, 1) k_fused(const float* __restrict__ fus_b) {
    extern __shared__ unsigned char dyn[];
    __half* As = (__half*)dyn;                    // [2][128][72]
    __half* Bs = (__half*)(dyn + SM_B_OFF);       // [2][288][72]
    float* A3s = (float*)(dyn + SM_A3_OFF);       // [384][3]
    float* Ls = (float*)(dyn + SM_LS_OFF);        // [128][3]
    float* Ws = (float*)(dyn + SM_WS_OFF);        // [128][3]
    float* stage = (float*)dyn;                   // [128][292] (epilogue, overlaps A/B)
    float* bnS = A3s;                             // [192] (epilogue, overlaps A3s)
    uint32_t smA = smem_u32(As);
    uint32_t smB = smem_u32(Bs);

    int tid = threadIdx.x;
    int lane = tid & 31, wid = tid >> 5;
    int wm = wid & 3, wn = wid >> 2;
    int gid = lane >> 2, tq = lane & 3;
    int m0 = blockIdx.x * 128;

    for (int i = tid; i < KW * 3; i += 512) A3s[i] = g_A3[i];

    const int Warr[6] = {288, 288, 288, 192, 192, 96};

#define LOAD_A(chunk, buf)                                                                  \
    {                                                                                       \
        _Pragma("unroll") for (int i = 0; i < 2; i++) {                                     \
            int idx = tid + i * 512;                                                        \
            int row = idx >> 3, seg = idx & 7;                                              \
            int srow = m0 + row; if (srow >= NN) srow = NN - 1;                             \
            const __half* src = g_Th + (size_t)srow * KW + (chunk) * 64 + seg * 8;          \
            uint32_t dst = smA + (((buf) * 128 + row) * 72 + seg * 8) * 2;                  \
            CP16(dst, src);                                                                 \
        }                                                                                   \
    }
#define LOAD_B(chunk, buf, wb)                                                              \
    {                                                                                       \
        _Pragma("unroll") for (int i = 0; i < 5; i++) {                                     \
            int idx = tid + i * 512;                                                        \
            int row = idx >> 3, seg = idx & 7;                                              \
            if (row < (wb)) {                                                               \
                const __half* src = g_Uf16 + (size_t)row * KW + (chunk) * 64 + seg * 8;     \
                uint32_t dst = smB + (((buf) * 288 + row) * 72 + seg * 8) * 2;              \
                CP16(dst, src);                                                             \
            }                                                                               \
        }                                                                                   \
    }

    float acc[2][9][4];
#pragma unroll
    for (int mt = 0; mt < 2; mt++)
#pragma unroll
        for (int nt = 0; nt < 9; nt++)
#pragma unroll
            for (int q = 0; q < 4; q++) acc[mt][nt][q] = 0.f;
    float Lacc = 0.f;
    int lr = tid / 3, lj = tid - (tid / 3) * 3;   // logits assignment (tid<384)

    LOAD_A(0, 0);
    LOAD_B(0, 0, 288);
    CPCOMMIT();

    for (int c = 0; c < 6; c++) {
        int buf = c & 1;
        if (c + 1 < 6) {
            LOAD_A(c + 1, buf ^ 1);
            LOAD_B(c + 1, buf ^ 1, Warr[c + 1]);
            CPCOMMIT();
            CPWAIT(1);
        } else {
            CPWAIT(0);
        }
        __syncthreads();

        const __half* Ab = As + (size_t)buf * 128 * 72;
        const __half* Bb = Bs + (size_t)buf * 288 * 72;
        if (c < 3)      do_chunk<288>(Ab, Bb, acc, wm, wn, gid, tq);
        else if (c < 5) do_chunk<192>(Ab, Bb, acc, wm, wn, gid, tq);
        else            do_chunk<96>(Ab, Bb, acc, wm, wn, gid, tq);

        // logits on the same A chunk (half2 loads, fp32 accumulate)
        if (tid < 384) {
            const __half2* Ar2 = (const __half2*)(Ab + lr * 72);
            const float* A3c = A3s + c * 192 + lj;
#pragma unroll 8
            for (int kk2 = 0; kk2 < 32; kk2++) {
                float2 f = __half22float2(Ar2[kk2]);
                Lacc += f.x * A3c[kk2 * 6] + f.y * A3c[kk2 * 6 + 3];
            }
        }
        __syncthreads();
    }

    // ---- epilogue ----
    if (tid < 384) Ls[tid] = Lacc;
    if (tid < 192) bnS[tid] = 0.f;
#pragma unroll
    for (int mt = 0; mt < 2; mt++) {
        int row = wm * 32 + mt * 16 + gid;
#pragma unroll
        for (int nt = 0; nt < 9; nt++) {
            int cc = wn * 72 + nt * 8 + tq * 2;
            *(float2*)(stage + row * STG_PITCH + cc) = make_float2(acc[mt][nt][0], acc[mt][nt][1]);
            *(float2*)(stage + (row + 8) * STG_PITCH + cc) = make_float2(acc[mt][nt][2], acc[mt][nt][3]);
        }
    }
    __syncthreads();

    if (tid < 128) {
        float l0 = Ls[tid * 3 + 0] + g_lconst[0];
        float l1 = Ls[tid * 3 + 1] + g_lconst[1];
        float l2 = Ls[tid * 3 + 2] + g_lconst[2];
        float m = fmaxf(l0, fmaxf(l1, l2));
        float e0 = __expf(l0 - m), e1 = __expf(l1 - m), e2 = __expf(l2 - m);
        float inv = 1.f / (e0 + e1 + e2);
        Ws[tid * 3 + 0] = e0 * inv;
        Ws[tid * 3 + 1] = e1 * inv;
        Ws[tid * 3 + 2] = e2 * inv;
    }
    __syncthreads();

    if (tid < 384) {
        int c = tid % 96, q = tid / 96;
        // N-block b holds scale 2-b
        float cs0 = g_cs[c], cs1 = g_cs[96 + c], cs2 = g_cs[192 + c];
        float fb = fus_b[c];
        float lsum = 0.f, lsq = 0.f;
        for (int r = q * 32; r < q * 32 + 32; r++) {
            int m = m0 + r;
            if (m >= NN) break;
            float w2s = Ws[r * 3 + 2];   // scale2 -> block 0
            float w1s = Ws[r * 3 + 1];   // scale1 -> block 1
            float w0s = Ws[r * 3 + 0];   // scale0 -> block 2
            const float* f = stage + r * STG_PITCH;
            float h = w2s * (f[c] + cs0) + w1s * (f[96 + c] + cs1) + w0s * (f[192 + c] + cs2) + fb;
            g_h[(size_t)m * C + c] = h;
            lsum += h;
            lsq += h * h;
        }
        atomicAdd(&bnS[c], lsum);
        atomicAdd(&bnS[96 + c], lsq);
    }
    __syncthreads();
    if (tid < 96) {
        atomicAdd(&g_sum[tid], bnS[tid]);
        atomicAdd(&g_sumsq[tid], bnS[96 + tid]);
    }
#undef LOAD_A
#undef LOAD_B
}

// ---------------- BN finalize + normalize (float4) + end-zero counters ----------------
__global__ void k_norm(const float* __restrict__ gamma, const float* __restrict__ beta,
                       float* __restrict__ out) {
    __shared__ float sc[C], sh[C];
    int tid = threadIdx.x;
    if (tid < C) {
        float mean = g_sum[tid] / (float)NN;
        float var = g_sumsq[tid] / (float)NN - mean * mean;
        var = fmaxf(var, 0.f);
        float s = gamma[tid] * rsqrtf(var + BN_EPS);
        sc[tid] = s;
        sh[tid] = beta[tid] - mean * s;
    }
    __syncthreads();
    int i = blockIdx.x * blockDim.x + tid;
    if (i < NN * 24) {
        int c4 = (i % 24) * 4;
        float4 v = *(const float4*)(g_h + (size_t)i * 4);
        v.x = fmaxf(fmaf(v.x, sc[c4 + 0], sh[c4 + 0]), 0.f);
        v.y = fmaxf(fmaf(v.y, sc[c4 + 1], sh[c4 + 1]), 0.f);
        v.z = fmaxf(fmaf(v.z, sc[c4 + 2], sh[c4 + 2]), 0.f);
        v.w = fmaxf(fmaf(v.w, sc[c4 + 3], sh[c4 + 3]), 0.f);
        *(float4*)(out + (size_t)i * 4) = v;
    }
    // end-zero the histogram counters for the NEXT invocation (k_edges atomics).
    // Deterministic: every call does identical work; globals are zero at module load.
    if (i < NN) { g_deg[i] = 0.f; g_cnt[i] = 0; }
}

// ---------------- launch ----------------
extern "C" void kernel_launch(void* const* d_in, const int* in_sizes, int n_in,
                              void* d_out, int out_size) {
    const float* x        = (const float*)d_in[0];
    const void* ei        = d_in[1];
    const float* w2       = (const float*)d_in[2];
    const float* b2       = (const float*)d_in[3];
    const float* w3       = (const float*)d_in[4];
    const float* b3       = (const float*)d_in[5];
    const float* w4       = (const float*)d_in[6];
    const float* b4       = (const float*)d_in[7];
    const float* attn_w   = (const float*)d_in[8];
    const float* attn_b   = (const float*)d_in[9];
    const float* fus_w    = (const float*)d_in[10];
    const float* fus_b    = (const float*)d_in[11];
    const float* bn_gamma = (const float*)d_in[12];
    const float* bn_beta  = (const float*)d_in[13];
    float* out = (float*)d_out;

    static int smem_set = 0;
    if (!smem_set) {
        cudaFuncSetAttribute(k_fused, cudaFuncAttributeMaxDynamicSharedMemorySize, FUSED_SMEM);
        smem_set = 1;
    }

    k_edges<<<(NN * 24 + 255) / 256, 256>>>(ei, x);          // 0
    k_scan_local<<<49, 256>>>();                              // 1
    k_scan_add<<<(NN + 255) / 256, 256>>>();                  // 2
    k_scatter<<<(NE + 255) / 256, 256>>>();                   // 3  <- profiled slot
    k_precompU<<<37, 256>>>(w2, w3, w4, fus_w, attn_w, b2, b3, b4, attn_b);

    // T1 = P(T0); T2 = 2*P(T1) - T0; T3 = 2*P(T2) - T1   (byte offsets into g_Th rows)
    k_spmm<<<6250, 256>>>(0, -1, 192, 1);
    k_spmm<<<6250, 256>>>(192, 0, 384, 0);
    k_spmm<<<6250, 256>>>(384, 192, 576, 0);

    k_fused<<<TILES, 512, FUSED_SMEM>>>(fus_b);

    k_norm<<<(NN * 24 + 255) / 256, 256>>>(bn_gamma, bn_beta, out);
}